// round 6
// baseline (speedup 1.0000x reference)
#include <cuda_runtime.h>
#include <cstdint>

// ---------------------------------------------------------------------------
// LargeLoss via radix-select on RAW INPUT BITS (softplus is monotone, so the
// kth-largest unobserved loss == softplus(kth-largest x among t<0)).
// R6 = R5 + cheap ballot-gated compaction in passB; passC scans only the
// ~|bucket p1| compacted keys.
//   init     : zero hist1, counters, load k
//   passA    : stream in+tg -> hist1 (top 12 key bits) + compact candidate
//              keys (shared-staged) + 2-bit class code per element
//   select 0 : pick 12-bit bucket p1, residual rank k1, mode; zero hist2
//   passB    : scan keys -> hist2 (bits 19:8 of in-bucket keys) + compact
//              in-bucket keys into g_keys2 (ballot-gated, rare path)
//   select 1 : pick 24-bit prefix p2, residual k2; zero hist3; pad g_keys2
//   passC    : scan g_keys2 -> hist3 (bits 7:0 where key>>8==p2)
//   select 2 : exact kth key -> g_thr = softplus(decode(key))
//   finalize : stream in + class codes -> losses, mask negs by (loss < thr)
// ---------------------------------------------------------------------------

#define N_MAX 10240000

__device__ unsigned g_keys[N_MAX];
__device__ unsigned g_keys2[N_MAX];
__device__ unsigned char g_code[N_MAX / 4 + 8];   // 2 bits/elem, 1 byte per float4
__device__ unsigned g_hist1[4096];
__device__ unsigned g_hist2[4096];
__device__ unsigned g_hist3[256];
__device__ unsigned g_cnt, g_cnt2;
__device__ unsigned g_k0, g_k1, g_k2;
__device__ unsigned g_p1, g_p2;
__device__ int      g_mode;   // 0 normal, 1 keep-all (k==0), 2 drop-all
__device__ float    g_thr;

// ---------------------------------------------------------------------------
__device__ __forceinline__ unsigned f2key(float x) {
    unsigned b = __float_as_uint(x);
    return (b & 0x80000000u) ? ~b : (b | 0x80000000u);
}
__device__ __forceinline__ float key2f(unsigned k) {
    unsigned b = (k & 0x80000000u) ? (k & 0x7FFFFFFFu) : ~k;
    return __uint_as_float(b);
}
__device__ __forceinline__ float neg_loss_f(float x) {   // softplus(x)
    return fmaxf(x, 0.0f) + log1pf(expf(-fabsf(x)));
}

// ---------------------------------------------------------------------------
__global__ void init_kernel(const int* __restrict__ kin) {
    int t = threadIdx.x;
    for (int i = t; i < 4096; i += blockDim.x) g_hist1[i] = 0u;
    if (t == 0) {
        g_cnt = 0u; g_cnt2 = 0u;
        int k = *kin;
        g_k0 = (k > 0) ? (unsigned)k : 0u;
    }
}

// ---------------------------------------------------------------------------
// Pass A: histogram (bits 31:20 of key), candidate key compaction, class code.
__global__ void passA_kernel(const float* __restrict__ in,
                             const float* __restrict__ tg, int n) {
    __shared__ unsigned hist[4096];
    __shared__ unsigned stage[4096];
    __shared__ unsigned s_cnt, s_base;

    const int tid = threadIdx.x, bs = blockDim.x;
    const int lane = tid & 31;
    for (int i = tid; i < 4096; i += bs) hist[i] = 0u;
    if (tid == 0) s_cnt = 0u;
    __syncthreads();

    const float4* in4 = (const float4*)in;
    const float4* tg4 = (const float4*)tg;
    const int n4 = n >> 2;
    const int step = gridDim.x * bs * 2;

    for (int base = blockIdx.x * bs * 2; base < n4; base += step) {
        int i0 = base + tid;
        int i1 = base + bs + tid;
        bool v0 = i0 < n4, v1 = i1 < n4;
        float4 x0, t0, x1, t1;
        if (v0) { x0 = in4[i0]; t0 = tg4[i0]; }
        if (v1) { x1 = in4[i1]; t1 = tg4[i1]; }

        // class per lane: 0 unobserved, 1 positive, 2 negative
        int c0 = 0, c1 = 0;
        if (v0) {
            unsigned a = (t0.x > 0.f) ? 1u : ((t0.x < 0.f) ? 2u : 0u);
            unsigned b = (t0.y > 0.f) ? 1u : ((t0.y < 0.f) ? 2u : 0u);
            unsigned c = (t0.z > 0.f) ? 1u : ((t0.z < 0.f) ? 2u : 0u);
            unsigned d = (t0.w > 0.f) ? 1u : ((t0.w < 0.f) ? 2u : 0u);
            g_code[i0] = (unsigned char)(a | (b << 2) | (c << 4) | (d << 6));
            c0 = (a == 2u) + (b == 2u) + (c == 2u) + (d == 2u);
        }
        if (v1) {
            unsigned a = (t1.x > 0.f) ? 1u : ((t1.x < 0.f) ? 2u : 0u);
            unsigned b = (t1.y > 0.f) ? 1u : ((t1.y < 0.f) ? 2u : 0u);
            unsigned c = (t1.z > 0.f) ? 1u : ((t1.z < 0.f) ? 2u : 0u);
            unsigned d = (t1.w > 0.f) ? 1u : ((t1.w < 0.f) ? 2u : 0u);
            g_code[i1] = (unsigned char)(a | (b << 2) | (c << 4) | (d << 6));
            c1 = (a == 2u) + (b == 2u) + (c == 2u) + (d == 2u);
        }
        unsigned cnt = (unsigned)(c0 + c1);

        unsigned inc = cnt;
#pragma unroll
        for (int d = 1; d < 32; d <<= 1) {
            unsigned u = __shfl_up_sync(0xffffffffu, inc, d);
            if (lane >= d) inc += u;
        }
        unsigned wtot = __shfl_sync(0xffffffffu, inc, 31);
        unsigned wbase = 0;
        if (lane == 0 && wtot) wbase = atomicAdd(&s_cnt, wtot);
        wbase = __shfl_sync(0xffffffffu, wbase, 0);
        unsigned p = wbase + (inc - cnt);

#define PUSH(xv, tv) do { if ((tv) < 0.f) {                       \
            unsigned kk = f2key(xv);                              \
            atomicAdd(&hist[kk >> 20], 1u);                       \
            stage[p++] = kk; } } while (0)
        if (v0) { PUSH(x0.x, t0.x); PUSH(x0.y, t0.y); PUSH(x0.z, t0.z); PUSH(x0.w, t0.w); }
        if (v1) { PUSH(x1.x, t1.x); PUSH(x1.y, t1.y); PUSH(x1.z, t1.z); PUSH(x1.w, t1.w); }
#undef PUSH

        __syncthreads();
        unsigned c = s_cnt;
        if (c >= 2048u) {
            if (tid == 0) s_base = atomicAdd(&g_cnt, c);
            __syncthreads();
            unsigned gb = s_base;
            for (unsigned j = tid; j < c; j += bs) g_keys[gb + j] = stage[j];
            __syncthreads();
            if (tid == 0) s_cnt = 0u;
            __syncthreads();
        }
    }

    // scalar tail (n % 4), block 0 only — uniform loop for warp ops
    if (blockIdx.x == 0) {
        for (int base = (n >> 2) << 2; base < n; base += bs) {
            int i = base + tid;
            unsigned cnt = 0; unsigned kk = 0;
            if (i < n && tg[i] < 0.f) { kk = f2key(in[i]); cnt = 1; atomicAdd(&hist[kk >> 20], 1u); }
            unsigned inc = cnt;
#pragma unroll
            for (int d = 1; d < 32; d <<= 1) {
                unsigned u = __shfl_up_sync(0xffffffffu, inc, d);
                if (lane >= d) inc += u;
            }
            unsigned wtot = __shfl_sync(0xffffffffu, inc, 31);
            unsigned wbase = 0;
            if (lane == 0 && wtot) wbase = atomicAdd(&s_cnt, wtot);
            wbase = __shfl_sync(0xffffffffu, wbase, 0);
            if (cnt) stage[wbase + inc - 1] = kk;
        }
    }

    __syncthreads();
    unsigned c = s_cnt;
    if (c > 0u) {
        if (tid == 0) s_base = atomicAdd(&g_cnt, c);
        __syncthreads();
        unsigned gb = s_base;
        for (unsigned j = tid; j < c; j += bs) g_keys[gb + j] = stage[j];
    }
    __syncthreads();
    for (int i = tid; i < 4096; i += bs) {
        unsigned hv = hist[i];
        if (hv) atomicAdd(&g_hist1[i], hv);
    }
}

// ---------------------------------------------------------------------------
// Pass B: refinement scan (bits 19:8 of in-bucket keys) + ballot-gated
// compaction of in-bucket keys into g_keys2. Uniform trip count.
__global__ void passB_kernel() {
    __shared__ unsigned hist[4096];
    __shared__ unsigned stage[4096];
    __shared__ unsigned s_cnt, s_base;

    const int tid = threadIdx.x, bs = blockDim.x;
    for (int i = tid; i < 4096; i += bs) hist[i] = 0u;
    if (tid == 0) s_cnt = 0u;
    __syncthreads();

    const unsigned cnt = g_cnt;
    const unsigned lo  = g_p1 << 20;   // bucket base in key space
    const uint4* k4 = (const uint4*)g_keys;
    const unsigned m4 = cnt >> 2;
    const unsigned S = gridDim.x * bs;
    const unsigned niter = (m4 + S - 1u) / S;
    unsigned i = blockIdx.x * bs + tid;

    for (unsigned it = 0; it < niter; ++it, i += S) {
        bool v = i < m4;
        uint4 u = v ? k4[i] : make_uint4(0xFFFFFFFFu, 0xFFFFFFFFu, 0xFFFFFFFFu, 0xFFFFFFFFu);
        unsigned d0 = u.x - lo, d1 = u.y - lo, d2 = u.z - lo, d3 = u.w - lo;
        bool m0 = d0 < 0x100000u, m1 = d1 < 0x100000u;
        bool m2 = d2 < 0x100000u, m3 = d3 < 0x100000u;
        if (m0) atomicAdd(&hist[d0 >> 8], 1u);
        if (m1) atomicAdd(&hist[d1 >> 8], 1u);
        if (m2) atomicAdd(&hist[d2 >> 8], 1u);
        if (m3) atomicAdd(&hist[d3 >> 8], 1u);

        // rare path: only warps containing at least one in-bucket key
        if (__ballot_sync(0xffffffffu, m0 | m1 | m2 | m3)) {
            if (m0) stage[atomicAdd(&s_cnt, 1u)] = u.x;
            if (m1) stage[atomicAdd(&s_cnt, 1u)] = u.y;
            if (m2) stage[atomicAdd(&s_cnt, 1u)] = u.z;
            if (m3) stage[atomicAdd(&s_cnt, 1u)] = u.w;
        }

        // overflow guard: per iteration a block adds <= bs*4 keys
        __syncthreads();
        unsigned sc = s_cnt;
        if (sc >= 2048u) {
            if (tid == 0) s_base = atomicAdd(&g_cnt2, sc);
            __syncthreads();
            unsigned gb = s_base;
            for (unsigned j = tid; j < sc; j += bs) g_keys2[gb + j] = stage[j];
            __syncthreads();
            if (tid == 0) s_cnt = 0u;
        }
        __syncthreads();
    }

    // scalar tail (cnt % 4), block 0 only
    if (blockIdx.x == 0) {
        for (unsigned j = (m4 << 2) + tid; j < cnt; j += bs) {
            unsigned kk = g_keys[j];
            unsigned d = kk - lo;
            if (d < 0x100000u) {
                atomicAdd(&hist[d >> 8], 1u);
                stage[atomicAdd(&s_cnt, 1u)] = kk;
            }
        }
    }

    __syncthreads();
    unsigned sc = s_cnt;
    if (sc > 0u) {
        if (tid == 0) s_base = atomicAdd(&g_cnt2, sc);
        __syncthreads();
        unsigned gb = s_base;
        for (unsigned j = tid; j < sc; j += bs) g_keys2[gb + j] = stage[j];
    }
    __syncthreads();
    for (int i2 = tid; i2 < 4096; i2 += bs) {
        unsigned hv = hist[i2];
        if (hv) atomicAdd(&g_hist2[i2], hv);
    }
}

// ---------------------------------------------------------------------------
// Pass C: bits 7:0 among compacted in-bucket keys with (key>>8)==p2.
__global__ void passC_kernel() {
    __shared__ unsigned hist[256];
    const int tid = threadIdx.x, bs = blockDim.x;
    if (tid < 256) hist[tid] = 0u;
    __syncthreads();

    const unsigned cnt2 = g_cnt2;
    const unsigned p2   = g_p2;
    const uint4* k4 = (const uint4*)g_keys2;
    const unsigned m4 = cnt2 >> 2;
    const unsigned S = gridDim.x * bs;
    for (unsigned i = blockIdx.x * bs + tid; i < m4; i += S) {
        uint4 u = k4[i];
        if ((u.x >> 8) == p2) atomicAdd(&hist[u.x & 0xFFu], 1u);
        if ((u.y >> 8) == p2) atomicAdd(&hist[u.y & 0xFFu], 1u);
        if ((u.z >> 8) == p2) atomicAdd(&hist[u.z & 0xFFu], 1u);
        if ((u.w >> 8) == p2) atomicAdd(&hist[u.w & 0xFFu], 1u);
    }
    if (blockIdx.x == 0) {
        for (unsigned j = (m4 << 2) + tid; j < cnt2; j += bs) {
            unsigned u = g_keys2[j];
            if ((u >> 8) == p2) atomicAdd(&hist[u & 0xFFu], 1u);
        }
    }
    __syncthreads();
    if (tid < 256) {
        unsigned hv = hist[tid];
        if (hv) atomicAdd(&g_hist3[tid], hv);
    }
}

// ---------------------------------------------------------------------------
// Single-block select (1024 threads, 4 bins each): suffix sums + rank locate.
__global__ void select_kernel(int stage) {
    __shared__ unsigned smW[32];
    __shared__ unsigned smE[32];
    __shared__ unsigned sTotal;

    const int tid  = threadIdx.x;
    const int lane = tid & 31;
    const int wid  = tid >> 5;

    const unsigned* hist = (stage == 0) ? g_hist1 : (stage == 1) ? g_hist2 : g_hist3;
    const int nbins      = (stage == 2) ? 256 : 4096;

    unsigned h0 = 0, h1 = 0, h2 = 0, h3 = 0;
    int b0 = tid * 4;
    if (b0 + 0 < nbins) h0 = hist[b0 + 0];
    if (b0 + 1 < nbins) h1 = hist[b0 + 1];
    if (b0 + 2 < nbins) h2 = hist[b0 + 2];
    if (b0 + 3 < nbins) h3 = hist[b0 + 3];
    unsigned s = h0 + h1 + h2 + h3;

    unsigned v = s;
#pragma unroll
    for (int d = 1; d < 32; d <<= 1) {
        unsigned u = __shfl_down_sync(0xffffffffu, v, d);
        if (lane + d < 32) v += u;
    }
    if (lane == 0) smW[wid] = v;
    __syncthreads();
    if (wid == 0) {
        unsigned wv = smW[lane];
        unsigned wi = wv;
#pragma unroll
        for (int d = 1; d < 32; d <<= 1) {
            unsigned u = __shfl_down_sync(0xffffffffu, wi, d);
            if (lane + d < 32) wi += u;
        }
        smE[lane] = wi - wv;
        if (lane == 0) sTotal = wi;
    }
    __syncthreads();
    unsigned sfx = v + smE[wid];

    if (tid == 0) {
        if (stage == 0) {
            unsigned kk = g_k0;
            g_mode = (kk == 0u) ? 1 : (kk > sTotal ? 2 : 0);
            g_p1 = 0u; g_k1 = 0u;
        } else if (stage == 1) {
            g_p2 = 0u; g_k2 = 0u;
        } else {
            int m = g_mode;
            if (m == 1) g_thr = __int_as_float(0x7f800000);  // +inf: keep all
            else if (m == 2) g_thr = 0.0f;                   // drop all negs
        }
    }
    if (stage == 0) { for (int i = tid; i < 4096; i += blockDim.x) g_hist2[i] = 0u; }
    if (stage == 1) {
        if (tid < 256) g_hist3[tid] = 0u;
        // pad compacted in-bucket keys to a multiple of 4 with sentinels
        unsigned c2 = g_cnt2;
        unsigned pad = (4u - (c2 & 3u)) & 3u;
        if ((unsigned)tid < pad) g_keys2[c2 + tid] = 0xFFFFFFFFu;
    }
    __syncthreads();

    int mode = g_mode;
    if (stage == 0) mode = (g_k0 == 0u) ? 1 : (g_k0 > sTotal ? 2 : 0);
    unsigned kk = (stage == 0) ? g_k0 : (stage == 1) ? g_k1 : g_k2;
    if (mode != 0 || kk == 0u) return;

    unsigned run = sfx;
    unsigned hh[4] = {h0, h1, h2, h3};
#pragma unroll
    for (int j = 0; j < 4; j++) {
        int bin = b0 + j;
        if (bin < nbins) {
            unsigned next = run - hh[j];
            if (run >= kk && next < kk) {
                if (stage == 0)      { g_p1 = (unsigned)bin;                g_k1 = kk - next; }
                else if (stage == 1) { g_p2 = (g_p1 << 12) | (unsigned)bin; g_k2 = kk - next; }
                else {
                    unsigned key = (g_p2 << 8) | (unsigned)bin;
                    g_thr = neg_loss_f(key2f(key));
                }
            }
            run = next;
        }
    }
}

// ---------------------------------------------------------------------------
__device__ __forceinline__ float lane_loss(float x, unsigned cls, float thr) {
    float ax  = fabsf(x);
    float lse = log1pf(expf(-ax));
    float pl  = fmaxf(-x, 0.0f) + lse;
    float nl  = fmaxf( x, 0.0f) + lse;
    float r = 0.0f;
    if (cls == 1u) r = pl;
    else if (cls == 2u) r = (nl < thr) ? nl : 0.0f;
    return r;
}
__device__ __forceinline__ float elem_loss_t(float x, float t, float thr) {
    unsigned cls = (t > 0.f) ? 1u : ((t < 0.f) ? 2u : 0u);
    return lane_loss(x, cls, thr);
}

__global__ void finalize_kernel(const float* __restrict__ in,
                                const float* __restrict__ tg,
                                float* __restrict__ out, int n) {
    const float thr = g_thr;
    const float4* in4 = (const float4*)in;
    float4* o4 = (float4*)out;
    const int n4 = n >> 2;
    const int S = gridDim.x * blockDim.x;
    int i = blockIdx.x * blockDim.x + threadIdx.x;

    for (; i + S < n4; i += 2 * S) {
        float4 x0 = in4[i];
        float4 x1 = in4[i + S];
        unsigned c0 = g_code[i];
        unsigned c1 = g_code[i + S];
        float4 o0, o1;
        o0.x = lane_loss(x0.x,  c0        & 3u, thr);
        o0.y = lane_loss(x0.y, (c0 >> 2)  & 3u, thr);
        o0.z = lane_loss(x0.z, (c0 >> 4)  & 3u, thr);
        o0.w = lane_loss(x0.w, (c0 >> 6)  & 3u, thr);
        o1.x = lane_loss(x1.x,  c1        & 3u, thr);
        o1.y = lane_loss(x1.y, (c1 >> 2)  & 3u, thr);
        o1.z = lane_loss(x1.z, (c1 >> 4)  & 3u, thr);
        o1.w = lane_loss(x1.w, (c1 >> 6)  & 3u, thr);
        o4[i] = o0;
        o4[i + S] = o1;
    }
    for (; i < n4; i += S) {
        float4 x0 = in4[i];
        unsigned c0 = g_code[i];
        float4 o0;
        o0.x = lane_loss(x0.x,  c0        & 3u, thr);
        o0.y = lane_loss(x0.y, (c0 >> 2)  & 3u, thr);
        o0.z = lane_loss(x0.z, (c0 >> 4)  & 3u, thr);
        o0.w = lane_loss(x0.w, (c0 >> 6)  & 3u, thr);
        o4[i] = o0;
    }
    if (blockIdx.x == 0) {
        for (int j = (n4 << 2) + threadIdx.x; j < n; j += blockDim.x)
            out[j] = elem_loss_t(in[j], tg[j], thr);
    }
}

// ---------------------------------------------------------------------------
extern "C" void kernel_launch(void* const* d_in, const int* in_sizes, int n_in,
                              void* d_out, int out_size) {
    const float* inp  = (const float*)d_in[0];
    const float* tgt  = (const float*)d_in[1];
    const int*   kptr = (const int*)d_in[2];
    float* out = (float*)d_out;
    const int n = in_sizes[0];

    init_kernel<<<1, 1024>>>(kptr);
    passA_kernel<<<1184, 256>>>(inp, tgt, n);
    select_kernel<<<1, 1024>>>(0);
    passB_kernel<<<1184, 256>>>();
    select_kernel<<<1, 1024>>>(1);
    passC_kernel<<<148, 256>>>();
    select_kernel<<<1, 1024>>>(2);
    finalize_kernel<<<1184, 256>>>(inp, tgt, out, n);
}

// round 7
// speedup vs baseline: 1.0373x; 1.0373x over previous
#include <cuda_runtime.h>
#include <cstdint>

// ---------------------------------------------------------------------------
// LargeLoss via radix-select on RAW INPUT BITS (softplus is monotone, so the
// kth-largest unobserved loss == softplus(kth-largest x among t<0)).
// R7 = R5 minus passC: passB resolves all remaining 20 bits in one scan via
// coarse smem hist (bits 19:8) + sparse global fine hist (all 20 bits).
//   init     : zero hist1 + 1M-bin fine hist, load k
//   passA    : stream in+tg -> hist1 (top 12 key bits) + compact candidate
//              keys (shared-staged) + 2-bit class code per element
//   select0  : pick 12-bit bucket p1, residual rank k1, mode; zero hist2
//   passB    : scan keys; in-bucket keys: smem hist2[d>>8] + global fine[d]
//   select12 : coarse suffix-select on hist2 -> b2; walk 256 fine bins ->
//              exact kth key -> g_thr = softplus(decode(key))
//   finalize : stream in + class codes -> losses, mask negs by (loss < thr)
// ---------------------------------------------------------------------------

#define N_MAX 10240000
#define FINE_BINS (1u << 20)

__device__ unsigned g_keys[N_MAX];
__device__ unsigned char g_code[N_MAX / 4 + 8];   // 2 bits/elem, 1 byte per float4
__device__ unsigned g_hist1[4096];
__device__ unsigned g_hist2[4096];
__device__ unsigned g_fine[FINE_BINS];            // 4 MB, zeroed each replay
__device__ unsigned g_cnt;
__device__ unsigned g_k0, g_k1;
__device__ unsigned g_p1;
__device__ int      g_mode;   // 0 normal, 1 keep-all (k==0), 2 drop-all
__device__ float    g_thr;

// ---------------------------------------------------------------------------
__device__ __forceinline__ unsigned f2key(float x) {
    unsigned b = __float_as_uint(x);
    return (b & 0x80000000u) ? ~b : (b | 0x80000000u);
}
__device__ __forceinline__ float key2f(unsigned k) {
    unsigned b = (k & 0x80000000u) ? (k & 0x7FFFFFFFu) : ~k;
    return __uint_as_float(b);
}
__device__ __forceinline__ float neg_loss_f(float x) {   // softplus(x)
    return fmaxf(x, 0.0f) + log1pf(expf(-fabsf(x)));
}

// ---------------------------------------------------------------------------
__global__ void init_kernel(const int* __restrict__ kin) {
    const unsigned t = blockIdx.x * blockDim.x + threadIdx.x;
    const unsigned S = gridDim.x * blockDim.x;
    uint4* f4 = (uint4*)g_fine;
    const unsigned M4 = FINE_BINS / 4;
    for (unsigned i = t; i < M4; i += S) f4[i] = make_uint4(0u, 0u, 0u, 0u);
    if (blockIdx.x == 0) {
        for (int i = threadIdx.x; i < 4096; i += blockDim.x) g_hist1[i] = 0u;
        if (threadIdx.x == 0) {
            g_cnt = 0u;
            int k = *kin;
            g_k0 = (k > 0) ? (unsigned)k : 0u;
        }
    }
}

// ---------------------------------------------------------------------------
// Pass A: histogram (bits 31:20 of key), candidate key compaction, class code.
__global__ void passA_kernel(const float* __restrict__ in,
                             const float* __restrict__ tg, int n) {
    __shared__ unsigned hist[4096];
    __shared__ unsigned stage[4096];
    __shared__ unsigned s_cnt, s_base;

    const int tid = threadIdx.x, bs = blockDim.x;
    const int lane = tid & 31;
    for (int i = tid; i < 4096; i += bs) hist[i] = 0u;
    if (tid == 0) s_cnt = 0u;
    __syncthreads();

    const float4* in4 = (const float4*)in;
    const float4* tg4 = (const float4*)tg;
    const int n4 = n >> 2;
    const int step = gridDim.x * bs * 2;

    for (int base = blockIdx.x * bs * 2; base < n4; base += step) {
        int i0 = base + tid;
        int i1 = base + bs + tid;
        bool v0 = i0 < n4, v1 = i1 < n4;
        float4 x0, t0, x1, t1;
        if (v0) { x0 = in4[i0]; t0 = tg4[i0]; }
        if (v1) { x1 = in4[i1]; t1 = tg4[i1]; }

        // class per lane: 0 unobserved, 1 positive, 2 negative
        int c0 = 0, c1 = 0;
        if (v0) {
            unsigned a = (t0.x > 0.f) ? 1u : ((t0.x < 0.f) ? 2u : 0u);
            unsigned b = (t0.y > 0.f) ? 1u : ((t0.y < 0.f) ? 2u : 0u);
            unsigned c = (t0.z > 0.f) ? 1u : ((t0.z < 0.f) ? 2u : 0u);
            unsigned d = (t0.w > 0.f) ? 1u : ((t0.w < 0.f) ? 2u : 0u);
            g_code[i0] = (unsigned char)(a | (b << 2) | (c << 4) | (d << 6));
            c0 = (a == 2u) + (b == 2u) + (c == 2u) + (d == 2u);
        }
        if (v1) {
            unsigned a = (t1.x > 0.f) ? 1u : ((t1.x < 0.f) ? 2u : 0u);
            unsigned b = (t1.y > 0.f) ? 1u : ((t1.y < 0.f) ? 2u : 0u);
            unsigned c = (t1.z > 0.f) ? 1u : ((t1.z < 0.f) ? 2u : 0u);
            unsigned d = (t1.w > 0.f) ? 1u : ((t1.w < 0.f) ? 2u : 0u);
            g_code[i1] = (unsigned char)(a | (b << 2) | (c << 4) | (d << 6));
            c1 = (a == 2u) + (b == 2u) + (c == 2u) + (d == 2u);
        }
        unsigned cnt = (unsigned)(c0 + c1);

        unsigned inc = cnt;
#pragma unroll
        for (int d = 1; d < 32; d <<= 1) {
            unsigned u = __shfl_up_sync(0xffffffffu, inc, d);
            if (lane >= d) inc += u;
        }
        unsigned wtot = __shfl_sync(0xffffffffu, inc, 31);
        unsigned wbase = 0;
        if (lane == 0 && wtot) wbase = atomicAdd(&s_cnt, wtot);
        wbase = __shfl_sync(0xffffffffu, wbase, 0);
        unsigned p = wbase + (inc - cnt);

#define PUSH(xv, tv) do { if ((tv) < 0.f) {                       \
            unsigned kk = f2key(xv);                              \
            atomicAdd(&hist[kk >> 20], 1u);                       \
            stage[p++] = kk; } } while (0)
        if (v0) { PUSH(x0.x, t0.x); PUSH(x0.y, t0.y); PUSH(x0.z, t0.z); PUSH(x0.w, t0.w); }
        if (v1) { PUSH(x1.x, t1.x); PUSH(x1.y, t1.y); PUSH(x1.z, t1.z); PUSH(x1.w, t1.w); }
#undef PUSH

        __syncthreads();
        unsigned c = s_cnt;
        if (c >= 2048u) {
            if (tid == 0) s_base = atomicAdd(&g_cnt, c);
            __syncthreads();
            unsigned gb = s_base;
            for (unsigned j = tid; j < c; j += bs) g_keys[gb + j] = stage[j];
            __syncthreads();
            if (tid == 0) s_cnt = 0u;
            __syncthreads();
        }
    }

    // scalar tail (n % 4), block 0 only — uniform loop for warp ops
    if (blockIdx.x == 0) {
        for (int base = (n >> 2) << 2; base < n; base += bs) {
            int i = base + tid;
            unsigned cnt = 0; unsigned kk = 0;
            if (i < n && tg[i] < 0.f) { kk = f2key(in[i]); cnt = 1; atomicAdd(&hist[kk >> 20], 1u); }
            unsigned inc = cnt;
#pragma unroll
            for (int d = 1; d < 32; d <<= 1) {
                unsigned u = __shfl_up_sync(0xffffffffu, inc, d);
                if (lane >= d) inc += u;
            }
            unsigned wtot = __shfl_sync(0xffffffffu, inc, 31);
            unsigned wbase = 0;
            if (lane == 0 && wtot) wbase = atomicAdd(&s_cnt, wtot);
            wbase = __shfl_sync(0xffffffffu, wbase, 0);
            if (cnt) stage[wbase + inc - 1] = kk;
        }
    }

    __syncthreads();
    unsigned c = s_cnt;
    if (c > 0u) {
        if (tid == 0) s_base = atomicAdd(&g_cnt, c);
        __syncthreads();
        unsigned gb = s_base;
        for (unsigned j = tid; j < c; j += bs) g_keys[gb + j] = stage[j];
    }
    __syncthreads();
    for (int i = tid; i < 4096; i += bs) {
        unsigned hv = hist[i];
        if (hv) atomicAdd(&g_hist1[i], hv);
    }
}

// ---------------------------------------------------------------------------
// Select stage 0: suffix sums of hist1, pick bucket p1 + residual rank k1.
__global__ void select0_kernel() {
    __shared__ unsigned smW[32];
    __shared__ unsigned smE[32];
    __shared__ unsigned sTotal;

    const int tid  = threadIdx.x;
    const int lane = tid & 31;
    const int wid  = tid >> 5;

    unsigned h0 = g_hist1[tid * 4 + 0];
    unsigned h1 = g_hist1[tid * 4 + 1];
    unsigned h2 = g_hist1[tid * 4 + 2];
    unsigned h3 = g_hist1[tid * 4 + 3];
    unsigned s = h0 + h1 + h2 + h3;

    unsigned v = s;
#pragma unroll
    for (int d = 1; d < 32; d <<= 1) {
        unsigned u = __shfl_down_sync(0xffffffffu, v, d);
        if (lane + d < 32) v += u;
    }
    if (lane == 0) smW[wid] = v;
    __syncthreads();
    if (wid == 0) {
        unsigned wv = smW[lane];
        unsigned wi = wv;
#pragma unroll
        for (int d = 1; d < 32; d <<= 1) {
            unsigned u = __shfl_down_sync(0xffffffffu, wi, d);
            if (lane + d < 32) wi += u;
        }
        smE[lane] = wi - wv;
        if (lane == 0) sTotal = wi;
    }
    __syncthreads();
    unsigned sfx = v + smE[wid];

    if (tid == 0) {
        unsigned kk = g_k0;
        g_mode = (kk == 0u) ? 1 : (kk > sTotal ? 2 : 0);
        g_p1 = 0u; g_k1 = 0u;
    }
    for (int i = tid; i < 4096; i += blockDim.x) g_hist2[i] = 0u;
    __syncthreads();

    unsigned kk = g_k0;
    if (kk == 0u || kk > sTotal) return;

    unsigned run = sfx;
    unsigned hh[4] = {h0, h1, h2, h3};
#pragma unroll
    for (int j = 0; j < 4; j++) {
        unsigned next = run - hh[j];
        if (run >= kk && next < kk) {
            g_p1 = (unsigned)(tid * 4 + j);
            g_k1 = kk - next;
        }
        run = next;
    }
}

// ---------------------------------------------------------------------------
// Pass B: in-bucket keys -> smem coarse hist (bits 19:8) + global fine hist
// (all 20 bits). The fine RED is rare (~1% of keys), off the hot path.
__global__ void passB_kernel() {
    __shared__ unsigned hist[4096];
    const int tid = threadIdx.x, bs = blockDim.x;
    for (int i = tid; i < 4096; i += bs) hist[i] = 0u;
    __syncthreads();

    const unsigned cnt = g_cnt;
    const unsigned lo  = g_p1 << 20;   // bucket base in key space
    const uint4* k4 = (const uint4*)g_keys;
    const unsigned m4 = cnt >> 2;
    const unsigned S = gridDim.x * bs;
    unsigned i = blockIdx.x * bs + tid;

#define PROC(e) do {                                              \
        unsigned d = (e) - lo;                                    \
        if (d < 0x100000u) {                                      \
            atomicAdd(&hist[d >> 8], 1u);                         \
            atomicAdd(&g_fine[d], 1u);                            \
        } } while (0)
    for (; i + S < m4; i += 2u * S) {
        uint4 a = k4[i], b = k4[i + S];
        PROC(a.x); PROC(a.y); PROC(a.z); PROC(a.w);
        PROC(b.x); PROC(b.y); PROC(b.z); PROC(b.w);
    }
    for (; i < m4; i += S) {
        uint4 a = k4[i];
        PROC(a.x); PROC(a.y); PROC(a.z); PROC(a.w);
    }
    if (blockIdx.x == 0) {
        for (unsigned j = (m4 << 2) + tid; j < cnt; j += bs) PROC(g_keys[j]);
    }
#undef PROC
    __syncthreads();
    for (int i2 = tid; i2 < 4096; i2 += bs) {
        unsigned hv = hist[i2];
        if (hv) atomicAdd(&g_hist2[i2], hv);
    }
}

// ---------------------------------------------------------------------------
// Select stages 1+2 fused: coarse suffix-select over hist2 (4096 bins of
// bits 19:8), then walk the 256 fine bins of the chosen coarse bin.
__global__ void select12_kernel() {
    __shared__ unsigned smW[32];
    __shared__ unsigned smE[32];
    __shared__ unsigned s_bin, s_krem;
    __shared__ unsigned fine[256];

    const int tid  = threadIdx.x;
    const int lane = tid & 31;
    const int wid  = tid >> 5;
    const int mode = g_mode;
    const unsigned k1 = g_k1;

    unsigned h0 = g_hist2[tid * 4 + 0];
    unsigned h1 = g_hist2[tid * 4 + 1];
    unsigned h2 = g_hist2[tid * 4 + 2];
    unsigned h3 = g_hist2[tid * 4 + 3];
    unsigned s = h0 + h1 + h2 + h3;

    unsigned v = s;
#pragma unroll
    for (int d = 1; d < 32; d <<= 1) {
        unsigned u = __shfl_down_sync(0xffffffffu, v, d);
        if (lane + d < 32) v += u;
    }
    if (lane == 0) smW[wid] = v;
    if (tid == 0) s_bin = 0u;
    __syncthreads();
    if (wid == 0) {
        unsigned wv = smW[lane];
        unsigned wi = wv;
#pragma unroll
        for (int d = 1; d < 32; d <<= 1) {
            unsigned u = __shfl_down_sync(0xffffffffu, wi, d);
            if (lane + d < 32) wi += u;
        }
        smE[lane] = wi - wv;
    }
    __syncthreads();
    unsigned sfx = v + smE[wid];

    if (mode == 0 && k1 != 0u) {
        unsigned run = sfx;
        unsigned hh[4] = {h0, h1, h2, h3};
#pragma unroll
        for (int j = 0; j < 4; j++) {
            unsigned next = run - hh[j];
            if (run >= k1 && next < k1) {
                s_bin = (unsigned)(tid * 4 + j);
                s_krem = k1 - next;
            }
            run = next;
        }
    }
    __syncthreads();

    if (mode != 0) {
        if (tid == 0)
            g_thr = (mode == 1) ? __int_as_float(0x7f800000) : 0.0f;
        return;
    }

    // fine phase: 256 bins of coarse bin s_bin
    unsigned b2 = s_bin;
    if (tid < 256) fine[tid] = g_fine[(b2 << 8) | (unsigned)tid];
    __syncthreads();
    if (tid == 0) {
        unsigned krem = s_krem;
        unsigned acc = 0;
        unsigned low = 0;
        for (int j = 255; j >= 0; --j) {
            acc += fine[j];
            if (acc >= krem) { low = (unsigned)j; break; }
        }
        unsigned key = (g_p1 << 20) | (b2 << 8) | low;
        g_thr = neg_loss_f(key2f(key));
    }
}

// ---------------------------------------------------------------------------
__device__ __forceinline__ float lane_loss(float x, unsigned cls, float thr) {
    float ax  = fabsf(x);
    float lse = log1pf(expf(-ax));
    float pl  = fmaxf(-x, 0.0f) + lse;
    float nl  = fmaxf( x, 0.0f) + lse;
    float r = 0.0f;
    if (cls == 1u) r = pl;
    else if (cls == 2u) r = (nl < thr) ? nl : 0.0f;
    return r;
}
__device__ __forceinline__ float elem_loss_t(float x, float t, float thr) {
    unsigned cls = (t > 0.f) ? 1u : ((t < 0.f) ? 2u : 0u);
    return lane_loss(x, cls, thr);
}

__global__ void finalize_kernel(const float* __restrict__ in,
                                const float* __restrict__ tg,
                                float* __restrict__ out, int n) {
    const float thr = g_thr;
    const float4* in4 = (const float4*)in;
    float4* o4 = (float4*)out;
    const int n4 = n >> 2;
    const int S = gridDim.x * blockDim.x;
    int i = blockIdx.x * blockDim.x + threadIdx.x;

    for (; i + S < n4; i += 2 * S) {
        float4 x0 = in4[i];
        float4 x1 = in4[i + S];
        unsigned c0 = g_code[i];
        unsigned c1 = g_code[i + S];
        float4 o0, o1;
        o0.x = lane_loss(x0.x,  c0        & 3u, thr);
        o0.y = lane_loss(x0.y, (c0 >> 2)  & 3u, thr);
        o0.z = lane_loss(x0.z, (c0 >> 4)  & 3u, thr);
        o0.w = lane_loss(x0.w, (c0 >> 6)  & 3u, thr);
        o1.x = lane_loss(x1.x,  c1        & 3u, thr);
        o1.y = lane_loss(x1.y, (c1 >> 2)  & 3u, thr);
        o1.z = lane_loss(x1.z, (c1 >> 4)  & 3u, thr);
        o1.w = lane_loss(x1.w, (c1 >> 6)  & 3u, thr);
        o4[i] = o0;
        o4[i + S] = o1;
    }
    for (; i < n4; i += S) {
        float4 x0 = in4[i];
        unsigned c0 = g_code[i];
        float4 o0;
        o0.x = lane_loss(x0.x,  c0        & 3u, thr);
        o0.y = lane_loss(x0.y, (c0 >> 2)  & 3u, thr);
        o0.z = lane_loss(x0.z, (c0 >> 4)  & 3u, thr);
        o0.w = lane_loss(x0.w, (c0 >> 6)  & 3u, thr);
        o4[i] = o0;
    }
    if (blockIdx.x == 0) {
        for (int j = (n4 << 2) + threadIdx.x; j < n; j += blockDim.x)
            out[j] = elem_loss_t(in[j], tg[j], thr);
    }
}

// ---------------------------------------------------------------------------
extern "C" void kernel_launch(void* const* d_in, const int* in_sizes, int n_in,
                              void* d_out, int out_size) {
    const float* inp  = (const float*)d_in[0];
    const float* tgt  = (const float*)d_in[1];
    const int*   kptr = (const int*)d_in[2];
    float* out = (float*)d_out;
    const int n = in_sizes[0];

    init_kernel<<<1184, 256>>>(kptr);
    passA_kernel<<<1184, 256>>>(inp, tgt, n);
    select0_kernel<<<1, 1024>>>();
    passB_kernel<<<1184, 256>>>();
    select12_kernel<<<1, 1024>>>();
    finalize_kernel<<<1184, 256>>>(inp, tgt, out, n);
}

// round 9
// speedup vs baseline: 1.0665x; 1.0281x over previous
#include <cuda_runtime.h>
#include <cstdint>

// ---------------------------------------------------------------------------
// LargeLoss via radix-select on RAW INPUT BITS (softplus is monotone, so the
// kth-largest unobserved loss == softplus(kth-largest x among t<0)).
// R9 = R8 (compile-fixed): (a) parallel fine-bin selection in select12,
// (b) MLP-4 batched loads in passB.
//   init     : zero hist1 + 1M-bin fine hist, load k
//   passA    : stream in+tg -> hist1 (top 12 key bits) + compact candidate
//              keys (shared-staged) + 2-bit class code per element
//   select0  : pick 12-bit bucket p1, residual rank k1, mode; zero hist2
//   passB    : scan keys; in-bucket keys: smem hist2[d>>8] + global fine[d]
//   select12 : coarse suffix-select on hist2 -> b2; parallel suffix-select
//              over 256 fine bins -> exact kth key -> g_thr
//   finalize : stream in + class codes -> losses, mask negs by (loss < thr)
// ---------------------------------------------------------------------------

#define N_MAX 10240000
#define FINE_BINS (1u << 20)

__device__ unsigned g_keys[N_MAX];
__device__ unsigned char g_code[N_MAX / 4 + 8];   // 2 bits/elem, 1 byte per float4
__device__ unsigned g_hist1[4096];
__device__ unsigned g_hist2[4096];
__device__ unsigned g_fine[FINE_BINS];            // 4 MB, zeroed each replay
__device__ unsigned g_cnt;
__device__ unsigned g_k0, g_k1;
__device__ unsigned g_p1;
__device__ int      g_mode;   // 0 normal, 1 keep-all (k==0), 2 drop-all
__device__ float    g_thr;

// ---------------------------------------------------------------------------
__device__ __forceinline__ unsigned f2key(float x) {
    unsigned b = __float_as_uint(x);
    return (b & 0x80000000u) ? ~b : (b | 0x80000000u);
}
__device__ __forceinline__ float key2f(unsigned k) {
    unsigned b = (k & 0x80000000u) ? (k & 0x7FFFFFFFu) : ~k;
    return __uint_as_float(b);
}
__device__ __forceinline__ float neg_loss_f(float x) {   // softplus(x)
    return fmaxf(x, 0.0f) + log1pf(expf(-fabsf(x)));
}

// ---------------------------------------------------------------------------
__global__ void init_kernel(const int* __restrict__ kin) {
    const unsigned t = blockIdx.x * blockDim.x + threadIdx.x;
    const unsigned S = gridDim.x * blockDim.x;
    uint4* f4 = (uint4*)g_fine;
    const unsigned M4 = FINE_BINS / 4;
    for (unsigned i = t; i < M4; i += S) f4[i] = make_uint4(0u, 0u, 0u, 0u);
    if (blockIdx.x == 0) {
        for (int i = threadIdx.x; i < 4096; i += blockDim.x) g_hist1[i] = 0u;
        if (threadIdx.x == 0) {
            g_cnt = 0u;
            int k = *kin;
            g_k0 = (k > 0) ? (unsigned)k : 0u;
        }
    }
}

// ---------------------------------------------------------------------------
// Pass A: histogram (bits 31:20 of key), candidate key compaction, class code.
__global__ void passA_kernel(const float* __restrict__ in,
                             const float* __restrict__ tg, int n) {
    __shared__ unsigned hist[4096];
    __shared__ unsigned stage[4096];
    __shared__ unsigned s_cnt, s_base;

    const int tid = threadIdx.x, bs = blockDim.x;
    const int lane = tid & 31;
    for (int i = tid; i < 4096; i += bs) hist[i] = 0u;
    if (tid == 0) s_cnt = 0u;
    __syncthreads();

    const float4* in4 = (const float4*)in;
    const float4* tg4 = (const float4*)tg;
    const int n4 = n >> 2;
    const int step = gridDim.x * bs * 2;

    for (int base = blockIdx.x * bs * 2; base < n4; base += step) {
        int i0 = base + tid;
        int i1 = base + bs + tid;
        bool v0 = i0 < n4, v1 = i1 < n4;
        float4 x0, t0, x1, t1;
        if (v0) { x0 = in4[i0]; t0 = tg4[i0]; }
        if (v1) { x1 = in4[i1]; t1 = tg4[i1]; }

        // class per lane: 0 unobserved, 1 positive, 2 negative
        int c0 = 0, c1 = 0;
        if (v0) {
            unsigned a = (t0.x > 0.f) ? 1u : ((t0.x < 0.f) ? 2u : 0u);
            unsigned b = (t0.y > 0.f) ? 1u : ((t0.y < 0.f) ? 2u : 0u);
            unsigned c = (t0.z > 0.f) ? 1u : ((t0.z < 0.f) ? 2u : 0u);
            unsigned d = (t0.w > 0.f) ? 1u : ((t0.w < 0.f) ? 2u : 0u);
            g_code[i0] = (unsigned char)(a | (b << 2) | (c << 4) | (d << 6));
            c0 = (a == 2u) + (b == 2u) + (c == 2u) + (d == 2u);
        }
        if (v1) {
            unsigned a = (t1.x > 0.f) ? 1u : ((t1.x < 0.f) ? 2u : 0u);
            unsigned b = (t1.y > 0.f) ? 1u : ((t1.y < 0.f) ? 2u : 0u);
            unsigned c = (t1.z > 0.f) ? 1u : ((t1.z < 0.f) ? 2u : 0u);
            unsigned d = (t1.w > 0.f) ? 1u : ((t1.w < 0.f) ? 2u : 0u);
            g_code[i1] = (unsigned char)(a | (b << 2) | (c << 4) | (d << 6));
            c1 = (a == 2u) + (b == 2u) + (c == 2u) + (d == 2u);
        }
        unsigned cnt = (unsigned)(c0 + c1);

        unsigned inc = cnt;
#pragma unroll
        for (int d = 1; d < 32; d <<= 1) {
            unsigned u = __shfl_up_sync(0xffffffffu, inc, d);
            if (lane >= d) inc += u;
        }
        unsigned wtot = __shfl_sync(0xffffffffu, inc, 31);
        unsigned wbase = 0;
        if (lane == 0 && wtot) wbase = atomicAdd(&s_cnt, wtot);
        wbase = __shfl_sync(0xffffffffu, wbase, 0);
        unsigned p = wbase + (inc - cnt);

#define PUSH(xv, tv) do { if ((tv) < 0.f) {                       \
            unsigned kk = f2key(xv);                              \
            atomicAdd(&hist[kk >> 20], 1u);                       \
            stage[p++] = kk; } } while (0)
        if (v0) { PUSH(x0.x, t0.x); PUSH(x0.y, t0.y); PUSH(x0.z, t0.z); PUSH(x0.w, t0.w); }
        if (v1) { PUSH(x1.x, t1.x); PUSH(x1.y, t1.y); PUSH(x1.z, t1.z); PUSH(x1.w, t1.w); }
#undef PUSH

        __syncthreads();
        unsigned c = s_cnt;
        if (c >= 2048u) {
            if (tid == 0) s_base = atomicAdd(&g_cnt, c);
            __syncthreads();
            unsigned gb = s_base;
            for (unsigned j = tid; j < c; j += bs) g_keys[gb + j] = stage[j];
            __syncthreads();
            if (tid == 0) s_cnt = 0u;
            __syncthreads();
        }
    }

    // scalar tail (n % 4), block 0 only — uniform loop for warp ops
    if (blockIdx.x == 0) {
        for (int base = (n >> 2) << 2; base < n; base += bs) {
            int i = base + tid;
            unsigned cnt = 0; unsigned kk = 0;
            if (i < n && tg[i] < 0.f) { kk = f2key(in[i]); cnt = 1; atomicAdd(&hist[kk >> 20], 1u); }
            unsigned inc = cnt;
#pragma unroll
            for (int d = 1; d < 32; d <<= 1) {
                unsigned u = __shfl_up_sync(0xffffffffu, inc, d);
                if (lane >= d) inc += u;
            }
            unsigned wtot = __shfl_sync(0xffffffffu, inc, 31);
            unsigned wbase = 0;
            if (lane == 0 && wtot) wbase = atomicAdd(&s_cnt, wtot);
            wbase = __shfl_sync(0xffffffffu, wbase, 0);
            if (cnt) stage[wbase + inc - 1] = kk;
        }
    }

    __syncthreads();
    unsigned c = s_cnt;
    if (c > 0u) {
        if (tid == 0) s_base = atomicAdd(&g_cnt, c);
        __syncthreads();
        unsigned gb = s_base;
        for (unsigned j = tid; j < c; j += bs) g_keys[gb + j] = stage[j];
    }
    __syncthreads();
    for (int i = tid; i < 4096; i += bs) {
        unsigned hv = hist[i];
        if (hv) atomicAdd(&g_hist1[i], hv);
    }
}

// ---------------------------------------------------------------------------
// Select stage 0: suffix sums of hist1, pick bucket p1 + residual rank k1.
__global__ void select0_kernel() {
    __shared__ unsigned smW[32];
    __shared__ unsigned smE[32];
    __shared__ unsigned sTotal;

    const int tid  = threadIdx.x;
    const int lane = tid & 31;
    const int wid  = tid >> 5;

    unsigned h0 = g_hist1[tid * 4 + 0];
    unsigned h1 = g_hist1[tid * 4 + 1];
    unsigned h2 = g_hist1[tid * 4 + 2];
    unsigned h3 = g_hist1[tid * 4 + 3];
    unsigned s = h0 + h1 + h2 + h3;

    unsigned v = s;
#pragma unroll
    for (int d = 1; d < 32; d <<= 1) {
        unsigned u = __shfl_down_sync(0xffffffffu, v, d);
        if (lane + d < 32) v += u;
    }
    if (lane == 0) smW[wid] = v;
    __syncthreads();
    if (wid == 0) {
        unsigned wv = smW[lane];
        unsigned wi = wv;
#pragma unroll
        for (int d = 1; d < 32; d <<= 1) {
            unsigned u = __shfl_down_sync(0xffffffffu, wi, d);
            if (lane + d < 32) wi += u;
        }
        smE[lane] = wi - wv;
        if (lane == 0) sTotal = wi;
    }
    __syncthreads();
    unsigned sfx = v + smE[wid];

    if (tid == 0) {
        unsigned kk = g_k0;
        g_mode = (kk == 0u) ? 1 : (kk > sTotal ? 2 : 0);
        g_p1 = 0u; g_k1 = 0u;
    }
    for (int i = tid; i < 4096; i += blockDim.x) g_hist2[i] = 0u;
    __syncthreads();

    unsigned kk = g_k0;
    if (kk == 0u || kk > sTotal) return;

    unsigned run = sfx;
    unsigned hh[4] = {h0, h1, h2, h3};
#pragma unroll
    for (int j = 0; j < 4; j++) {
        unsigned next = run - hh[j];
        if (run >= kk && next < kk) {
            g_p1 = (unsigned)(tid * 4 + j);
            g_k1 = kk - next;
        }
        run = next;
    }
}

// ---------------------------------------------------------------------------
// Pass B: in-bucket keys -> smem coarse hist (bits 19:8) + global fine hist
// (all 20 bits). MLP-4 batched loads; only the last iteration is predicated.
__global__ void passB_kernel() {
    __shared__ unsigned hist[4096];
    const int tid = threadIdx.x, bs = blockDim.x;
    for (int i = tid; i < 4096; i += bs) hist[i] = 0u;
    __syncthreads();

    const unsigned cnt = g_cnt;
    const unsigned lo  = g_p1 << 20;   // bucket base in key space
    const uint4* k4 = (const uint4*)g_keys;
    const unsigned m4 = cnt >> 2;
    const unsigned S = gridDim.x * bs;
    const unsigned niter = (m4 + S - 1u) / S;
    const unsigned full  = (niter > 0u) ? niter - 1u : 0u;  // provably in-range
    unsigned i = blockIdx.x * bs + tid;
    unsigned it = 0;

#define PROC(e) do {                                              \
        unsigned _dv = (e) - lo;                                  \
        if (_dv < 0x100000u) {                                    \
            atomicAdd(&hist[_dv >> 8], 1u);                       \
            atomicAdd(&g_fine[_dv], 1u);                          \
        } } while (0)
#define PROCQ(q) do { PROC((q).x); PROC((q).y); PROC((q).z); PROC((q).w); } while (0)
    for (; it + 4u <= full; it += 4u, i += 4u * S) {
        uint4 q0 = k4[i];
        uint4 q1 = k4[i + S];
        uint4 q2 = k4[i + 2u * S];
        uint4 q3 = k4[i + 3u * S];
        PROCQ(q0); PROCQ(q1); PROCQ(q2); PROCQ(q3);
    }
    for (; it < full; ++it, i += S) { uint4 q0 = k4[i]; PROCQ(q0); }
    if (it < niter && i < m4) { uint4 q0 = k4[i]; PROCQ(q0); }
    if (blockIdx.x == 0) {
        for (unsigned j = (m4 << 2) + tid; j < cnt; j += bs) PROC(g_keys[j]);
    }
#undef PROCQ
#undef PROC
    __syncthreads();
    for (int i2 = tid; i2 < 4096; i2 += bs) {
        unsigned hv = hist[i2];
        if (hv) atomicAdd(&g_hist2[i2], hv);
    }
}

// ---------------------------------------------------------------------------
// Select stages 1+2 fused: coarse suffix-select over hist2 (4096 bins of
// bits 19:8), then PARALLEL suffix-select over the 256 fine bins.
__global__ void select12_kernel() {
    __shared__ unsigned smW[32];
    __shared__ unsigned smE[32];
    __shared__ unsigned s_bin, s_krem;
    __shared__ unsigned fwsum[8], fwsuf[8];

    const int tid  = threadIdx.x;
    const int lane = tid & 31;
    const int wid  = tid >> 5;
    const int mode = g_mode;
    const unsigned k1 = g_k1;

    unsigned h0 = g_hist2[tid * 4 + 0];
    unsigned h1 = g_hist2[tid * 4 + 1];
    unsigned h2 = g_hist2[tid * 4 + 2];
    unsigned h3 = g_hist2[tid * 4 + 3];
    unsigned s = h0 + h1 + h2 + h3;

    unsigned v = s;
#pragma unroll
    for (int d = 1; d < 32; d <<= 1) {
        unsigned u = __shfl_down_sync(0xffffffffu, v, d);
        if (lane + d < 32) v += u;
    }
    if (lane == 0) smW[wid] = v;
    if (tid == 0) s_bin = 0u;
    __syncthreads();
    if (wid == 0) {
        unsigned wv = smW[lane];
        unsigned wi = wv;
#pragma unroll
        for (int d = 1; d < 32; d <<= 1) {
            unsigned u = __shfl_down_sync(0xffffffffu, wi, d);
            if (lane + d < 32) wi += u;
        }
        smE[lane] = wi - wv;
    }
    __syncthreads();
    unsigned sfx = v + smE[wid];

    if (mode == 0 && k1 != 0u) {
        unsigned run = sfx;
        unsigned hh[4] = {h0, h1, h2, h3};
#pragma unroll
        for (int j = 0; j < 4; j++) {
            unsigned next = run - hh[j];
            if (run >= k1 && next < k1) {
                s_bin = (unsigned)(tid * 4 + j);
                s_krem = k1 - next;
            }
            run = next;
        }
    }
    __syncthreads();

    if (mode != 0) {
        if (tid == 0)
            g_thr = (mode == 1) ? __int_as_float(0x7f800000) : 0.0f;
        return;
    }

    // fine phase: parallel suffix-select over 256 bins of coarse bin s_bin
    const unsigned b2 = s_bin;
    const unsigned krem = s_krem;
    unsigned fh = 0, fv = 0;
    if (tid < 256) {
        fh = g_fine[(b2 << 8) | (unsigned)tid];
        fv = fh;
#pragma unroll
        for (int d = 1; d < 32; d <<= 1) {
            unsigned u = __shfl_down_sync(0xffffffffu, fv, d);
            if (lane + d < 32) fv += u;
        }
        if (lane == 0) fwsum[wid] = fv;
    }
    __syncthreads();
    if (tid < 8) {
        unsigned acc = 0;
        for (int j = tid + 1; j < 8; j++) acc += fwsum[j];
        fwsuf[tid] = acc;
    }
    __syncthreads();
    if (tid < 256) {
        unsigned fsfx = fv + fwsuf[wid];       // suffix starting at this bin
        unsigned nxt = fsfx - fh;
        if (fsfx >= krem && nxt < krem) {
            unsigned key = (g_p1 << 20) | (b2 << 8) | (unsigned)tid;
            g_thr = neg_loss_f(key2f(key));
        }
    }
}

// ---------------------------------------------------------------------------
__device__ __forceinline__ float lane_loss(float x, unsigned cls, float thr) {
    float ax  = fabsf(x);
    float lse = log1pf(expf(-ax));
    float pl  = fmaxf(-x, 0.0f) + lse;
    float nl  = fmaxf( x, 0.0f) + lse;
    float r = 0.0f;
    if (cls == 1u) r = pl;
    else if (cls == 2u) r = (nl < thr) ? nl : 0.0f;
    return r;
}
__device__ __forceinline__ float elem_loss_t(float x, float t, float thr) {
    unsigned cls = (t > 0.f) ? 1u : ((t < 0.f) ? 2u : 0u);
    return lane_loss(x, cls, thr);
}

__global__ void finalize_kernel(const float* __restrict__ in,
                                const float* __restrict__ tg,
                                float* __restrict__ out, int n) {
    const float thr = g_thr;
    const float4* in4 = (const float4*)in;
    float4* o4 = (float4*)out;
    const int n4 = n >> 2;
    const int S = gridDim.x * blockDim.x;
    int i = blockIdx.x * blockDim.x + threadIdx.x;

    for (; i + S < n4; i += 2 * S) {
        float4 x0 = in4[i];
        float4 x1 = in4[i + S];
        unsigned c0 = g_code[i];
        unsigned c1 = g_code[i + S];
        float4 o0, o1;
        o0.x = lane_loss(x0.x,  c0        & 3u, thr);
        o0.y = lane_loss(x0.y, (c0 >> 2)  & 3u, thr);
        o0.z = lane_loss(x0.z, (c0 >> 4)  & 3u, thr);
        o0.w = lane_loss(x0.w, (c0 >> 6)  & 3u, thr);
        o1.x = lane_loss(x1.x,  c1        & 3u, thr);
        o1.y = lane_loss(x1.y, (c1 >> 2)  & 3u, thr);
        o1.z = lane_loss(x1.z, (c1 >> 4)  & 3u, thr);
        o1.w = lane_loss(x1.w, (c1 >> 6)  & 3u, thr);
        o4[i] = o0;
        o4[i + S] = o1;
    }
    for (; i < n4; i += S) {
        float4 x0 = in4[i];
        unsigned c0 = g_code[i];
        float4 o0;
        o0.x = lane_loss(x0.x,  c0        & 3u, thr);
        o0.y = lane_loss(x0.y, (c0 >> 2)  & 3u, thr);
        o0.z = lane_loss(x0.z, (c0 >> 4)  & 3u, thr);
        o0.w = lane_loss(x0.w, (c0 >> 6)  & 3u, thr);
        o4[i] = o0;
    }
    if (blockIdx.x == 0) {
        for (int j = (n4 << 2) + threadIdx.x; j < n; j += blockDim.x)
            out[j] = elem_loss_t(in[j], tg[j], thr);
    }
}

// ---------------------------------------------------------------------------
extern "C" void kernel_launch(void* const* d_in, const int* in_sizes, int n_in,
                              void* d_out, int out_size) {
    const float* inp  = (const float*)d_in[0];
    const float* tgt  = (const float*)d_in[1];
    const int*   kptr = (const int*)d_in[2];
    float* out = (float*)d_out;
    const int n = in_sizes[0];

    init_kernel<<<1184, 256>>>(kptr);
    passA_kernel<<<1184, 256>>>(inp, tgt, n);
    select0_kernel<<<1, 1024>>>();
    passB_kernel<<<1184, 256>>>();
    select12_kernel<<<1, 1024>>>();
    finalize_kernel<<<1184, 256>>>(inp, tgt, out, n);
}

// round 10
// speedup vs baseline: 1.2779x; 1.1983x over previous
#include <cuda_runtime.h>
#include <cstdint>

// ---------------------------------------------------------------------------
// LargeLoss via radix-select on RAW INPUT BITS (softplus is monotone, so the
// kth-largest unobserved loss == softplus(kth-largest x among t<0)).
// R10: 5 launches, fast transcendentals, R7 passB loop.
//   passA    : zero g_fine; stream in+tg -> hist1 (top 12 key bits) +
//              compacted candidate keys + 2-bit class code per element
//   select0  : read k; pick 12-bit bucket p1, residual k1, mode;
//              re-zero hist1; zero hist2
//   passB    : scan keys; in-bucket keys: smem hist2[d>>8] + global fine[d]
//   select12 : coarse suffix-select on hist2 -> b2; parallel suffix-select
//              over 256 fine bins -> exact kth key -> g_thr; zero g_cnt
//   finalize : stream in + class codes -> losses, mask negs by (loss < thr)
// ---------------------------------------------------------------------------

#define N_MAX 10240000
#define FINE_BINS (1u << 20)

__device__ unsigned g_keys[N_MAX];
__device__ unsigned char g_code[N_MAX / 4 + 8];   // 2 bits/elem, 1 byte per float4
__device__ unsigned g_hist1[4096];                // zeroed by select0 after use
__device__ unsigned g_hist2[4096];                // zeroed by select0 before passB
__device__ unsigned g_fine[FINE_BINS];            // 4 MB, zeroed by passA
__device__ unsigned g_cnt;                        // zeroed by select12
__device__ unsigned g_k1;
__device__ unsigned g_p1;
__device__ int      g_mode;   // 0 normal, 1 keep-all (k==0), 2 drop-all
__device__ float    g_thr;

// ---------------------------------------------------------------------------
__device__ __forceinline__ unsigned f2key(float x) {
    unsigned b = __float_as_uint(x);
    return (b & 0x80000000u) ? ~b : (b | 0x80000000u);
}
__device__ __forceinline__ float key2f(unsigned k) {
    unsigned b = (k & 0x80000000u) ? (k & 0x7FFFFFFFu) : ~k;
    return __uint_as_float(b);
}
// fast softplus pieces: lse = log(1 + e^-|x|), via MUFU intrinsics.
__device__ __forceinline__ float lse_fast(float ax) {
    return __logf(1.0f + __expf(-ax));
}
__device__ __forceinline__ float neg_loss_f(float x) {   // softplus(x)
    return fmaxf(x, 0.0f) + lse_fast(fabsf(x));
}

// ---------------------------------------------------------------------------
// Pass A: zero g_fine; histogram (bits 31:20 of key), candidate key
// compaction (shared-staged), class code per float4.
__global__ void passA_kernel(const float* __restrict__ in,
                             const float* __restrict__ tg, int n) {
    __shared__ unsigned hist[4096];
    __shared__ unsigned stage[4096];
    __shared__ unsigned s_cnt, s_base;

    const int tid = threadIdx.x, bs = blockDim.x;
    const int lane = tid & 31;
    for (int i = tid; i < 4096; i += bs) hist[i] = 0u;
    if (tid == 0) s_cnt = 0u;

    // zero the fine histogram (consumed by passB/select12 later this replay)
    {
        const unsigned t = blockIdx.x * bs + tid;
        const unsigned S = gridDim.x * bs;
        uint4* f4 = (uint4*)g_fine;
        const unsigned M4 = FINE_BINS / 4;
        for (unsigned i = t; i < M4; i += S) f4[i] = make_uint4(0u, 0u, 0u, 0u);
    }
    __syncthreads();

    const float4* in4 = (const float4*)in;
    const float4* tg4 = (const float4*)tg;
    const int n4 = n >> 2;
    const int step = gridDim.x * bs * 2;

    for (int base = blockIdx.x * bs * 2; base < n4; base += step) {
        int i0 = base + tid;
        int i1 = base + bs + tid;
        bool v0 = i0 < n4, v1 = i1 < n4;
        float4 x0, t0, x1, t1;
        if (v0) { x0 = in4[i0]; t0 = tg4[i0]; }
        if (v1) { x1 = in4[i1]; t1 = tg4[i1]; }

        // class per lane: 0 unobserved, 1 positive, 2 negative
        int c0 = 0, c1 = 0;
        if (v0) {
            unsigned a = (t0.x > 0.f) ? 1u : ((t0.x < 0.f) ? 2u : 0u);
            unsigned b = (t0.y > 0.f) ? 1u : ((t0.y < 0.f) ? 2u : 0u);
            unsigned c = (t0.z > 0.f) ? 1u : ((t0.z < 0.f) ? 2u : 0u);
            unsigned d = (t0.w > 0.f) ? 1u : ((t0.w < 0.f) ? 2u : 0u);
            g_code[i0] = (unsigned char)(a | (b << 2) | (c << 4) | (d << 6));
            c0 = (a == 2u) + (b == 2u) + (c == 2u) + (d == 2u);
        }
        if (v1) {
            unsigned a = (t1.x > 0.f) ? 1u : ((t1.x < 0.f) ? 2u : 0u);
            unsigned b = (t1.y > 0.f) ? 1u : ((t1.y < 0.f) ? 2u : 0u);
            unsigned c = (t1.z > 0.f) ? 1u : ((t1.z < 0.f) ? 2u : 0u);
            unsigned d = (t1.w > 0.f) ? 1u : ((t1.w < 0.f) ? 2u : 0u);
            g_code[i1] = (unsigned char)(a | (b << 2) | (c << 4) | (d << 6));
            c1 = (a == 2u) + (b == 2u) + (c == 2u) + (d == 2u);
        }
        unsigned cnt = (unsigned)(c0 + c1);

        unsigned inc = cnt;
#pragma unroll
        for (int d = 1; d < 32; d <<= 1) {
            unsigned u = __shfl_up_sync(0xffffffffu, inc, d);
            if (lane >= d) inc += u;
        }
        unsigned wtot = __shfl_sync(0xffffffffu, inc, 31);
        unsigned wbase = 0;
        if (lane == 0 && wtot) wbase = atomicAdd(&s_cnt, wtot);
        wbase = __shfl_sync(0xffffffffu, wbase, 0);
        unsigned p = wbase + (inc - cnt);

#define PUSH(xv, tv) do { if ((tv) < 0.f) {                       \
            unsigned kk = f2key(xv);                              \
            atomicAdd(&hist[kk >> 20], 1u);                       \
            stage[p++] = kk; } } while (0)
        if (v0) { PUSH(x0.x, t0.x); PUSH(x0.y, t0.y); PUSH(x0.z, t0.z); PUSH(x0.w, t0.w); }
        if (v1) { PUSH(x1.x, t1.x); PUSH(x1.y, t1.y); PUSH(x1.z, t1.z); PUSH(x1.w, t1.w); }
#undef PUSH

        __syncthreads();
        unsigned c = s_cnt;
        if (c >= 2048u) {
            if (tid == 0) s_base = atomicAdd(&g_cnt, c);
            __syncthreads();
            unsigned gb = s_base;
            for (unsigned j = tid; j < c; j += bs) g_keys[gb + j] = stage[j];
            __syncthreads();
            if (tid == 0) s_cnt = 0u;
            __syncthreads();
        }
    }

    // scalar tail (n % 4), block 0 only — uniform loop for warp ops
    if (blockIdx.x == 0) {
        for (int base = (n >> 2) << 2; base < n; base += bs) {
            int i = base + tid;
            unsigned cnt = 0; unsigned kk = 0;
            if (i < n && tg[i] < 0.f) { kk = f2key(in[i]); cnt = 1; atomicAdd(&hist[kk >> 20], 1u); }
            unsigned inc = cnt;
#pragma unroll
            for (int d = 1; d < 32; d <<= 1) {
                unsigned u = __shfl_up_sync(0xffffffffu, inc, d);
                if (lane >= d) inc += u;
            }
            unsigned wtot = __shfl_sync(0xffffffffu, inc, 31);
            unsigned wbase = 0;
            if (lane == 0 && wtot) wbase = atomicAdd(&s_cnt, wtot);
            wbase = __shfl_sync(0xffffffffu, wbase, 0);
            if (cnt) stage[wbase + inc - 1] = kk;
        }
    }

    __syncthreads();
    unsigned c = s_cnt;
    if (c > 0u) {
        if (tid == 0) s_base = atomicAdd(&g_cnt, c);
        __syncthreads();
        unsigned gb = s_base;
        for (unsigned j = tid; j < c; j += bs) g_keys[gb + j] = stage[j];
    }
    __syncthreads();
    for (int i = tid; i < 4096; i += bs) {
        unsigned hv = hist[i];
        if (hv) atomicAdd(&g_hist1[i], hv);
    }
}

// ---------------------------------------------------------------------------
// Select stage 0: read k from input; suffix sums of hist1; pick bucket p1
// + residual rank k1; re-zero hist1 (next replay) and hist2 (this replay).
__global__ void select0_kernel(const int* __restrict__ kin) {
    __shared__ unsigned smW[32];
    __shared__ unsigned smE[32];
    __shared__ unsigned sTotal;

    const int tid  = threadIdx.x;
    const int lane = tid & 31;
    const int wid  = tid >> 5;

    unsigned h0 = g_hist1[tid * 4 + 0];
    unsigned h1 = g_hist1[tid * 4 + 1];
    unsigned h2 = g_hist1[tid * 4 + 2];
    unsigned h3 = g_hist1[tid * 4 + 3];
    unsigned s = h0 + h1 + h2 + h3;

    unsigned v = s;
#pragma unroll
    for (int d = 1; d < 32; d <<= 1) {
        unsigned u = __shfl_down_sync(0xffffffffu, v, d);
        if (lane + d < 32) v += u;
    }
    if (lane == 0) smW[wid] = v;
    __syncthreads();
    if (wid == 0) {
        unsigned wv = smW[lane];
        unsigned wi = wv;
#pragma unroll
        for (int d = 1; d < 32; d <<= 1) {
            unsigned u = __shfl_down_sync(0xffffffffu, wi, d);
            if (lane + d < 32) wi += u;
        }
        smE[lane] = wi - wv;
        if (lane == 0) sTotal = wi;
    }
    __syncthreads();
    unsigned sfx = v + smE[wid];

    int kraw = *kin;
    unsigned kk = (kraw > 0) ? (unsigned)kraw : 0u;

    if (tid == 0) {
        g_mode = (kk == 0u) ? 1 : (kk > sTotal ? 2 : 0);
        g_p1 = 0u; g_k1 = 0u;
    }
    // hist1 consumed -> zero for next replay; hist2 zeroed for passB now
    for (int i = tid; i < 4096; i += blockDim.x) { g_hist1[i] = 0u; g_hist2[i] = 0u; }
    __syncthreads();

    if (kk == 0u || kk > sTotal) return;

    unsigned run = sfx;
    unsigned hh[4] = {h0, h1, h2, h3};
#pragma unroll
    for (int j = 0; j < 4; j++) {
        unsigned next = run - hh[j];
        if (run >= kk && next < kk) {
            g_p1 = (unsigned)(tid * 4 + j);
            g_k1 = kk - next;
        }
        run = next;
    }
}

// ---------------------------------------------------------------------------
// Pass B: in-bucket keys -> smem coarse hist (bits 19:8) + global fine hist
// (all 20 bits). R7's simple 2xS loop (empirically fastest).
__global__ void passB_kernel() {
    __shared__ unsigned hist[4096];
    const int tid = threadIdx.x, bs = blockDim.x;
    for (int i = tid; i < 4096; i += bs) hist[i] = 0u;
    __syncthreads();

    const unsigned cnt = g_cnt;
    const unsigned lo  = g_p1 << 20;   // bucket base in key space
    const uint4* k4 = (const uint4*)g_keys;
    const unsigned m4 = cnt >> 2;
    const unsigned S = gridDim.x * bs;
    unsigned i = blockIdx.x * bs + tid;

#define PROC(e) do {                                              \
        unsigned _dv = (e) - lo;                                  \
        if (_dv < 0x100000u) {                                    \
            atomicAdd(&hist[_dv >> 8], 1u);                       \
            atomicAdd(&g_fine[_dv], 1u);                          \
        } } while (0)
#define PROCQ(q) do { PROC((q).x); PROC((q).y); PROC((q).z); PROC((q).w); } while (0)
    for (; i + S < m4; i += 2u * S) {
        uint4 qa = k4[i], qb = k4[i + S];
        PROCQ(qa); PROCQ(qb);
    }
    for (; i < m4; i += S) { uint4 qa = k4[i]; PROCQ(qa); }
    if (blockIdx.x == 0) {
        for (unsigned j = (m4 << 2) + tid; j < cnt; j += bs) PROC(g_keys[j]);
    }
#undef PROCQ
#undef PROC
    __syncthreads();
    for (int i2 = tid; i2 < 4096; i2 += bs) {
        unsigned hv = hist[i2];
        if (hv) atomicAdd(&g_hist2[i2], hv);
    }
}

// ---------------------------------------------------------------------------
// Select stages 1+2 fused: coarse suffix-select over hist2, then PARALLEL
// suffix-select over the 256 fine bins. Also zeroes g_cnt for next replay.
__global__ void select12_kernel() {
    __shared__ unsigned smW[32];
    __shared__ unsigned smE[32];
    __shared__ unsigned s_bin, s_krem;
    __shared__ unsigned fwsum[8], fwsuf[8];

    const int tid  = threadIdx.x;
    const int lane = tid & 31;
    const int wid  = tid >> 5;
    const int mode = g_mode;
    const unsigned k1 = g_k1;

    if (tid == 0) g_cnt = 0u;   // consumed by passB; reset for next replay

    unsigned h0 = g_hist2[tid * 4 + 0];
    unsigned h1 = g_hist2[tid * 4 + 1];
    unsigned h2 = g_hist2[tid * 4 + 2];
    unsigned h3 = g_hist2[tid * 4 + 3];
    unsigned s = h0 + h1 + h2 + h3;

    unsigned v = s;
#pragma unroll
    for (int d = 1; d < 32; d <<= 1) {
        unsigned u = __shfl_down_sync(0xffffffffu, v, d);
        if (lane + d < 32) v += u;
    }
    if (lane == 0) smW[wid] = v;
    if (tid == 0) s_bin = 0u;
    __syncthreads();
    if (wid == 0) {
        unsigned wv = smW[lane];
        unsigned wi = wv;
#pragma unroll
        for (int d = 1; d < 32; d <<= 1) {
            unsigned u = __shfl_down_sync(0xffffffffu, wi, d);
            if (lane + d < 32) wi += u;
        }
        smE[lane] = wi - wv;
    }
    __syncthreads();
    unsigned sfx = v + smE[wid];

    if (mode == 0 && k1 != 0u) {
        unsigned run = sfx;
        unsigned hh[4] = {h0, h1, h2, h3};
#pragma unroll
        for (int j = 0; j < 4; j++) {
            unsigned next = run - hh[j];
            if (run >= k1 && next < k1) {
                s_bin = (unsigned)(tid * 4 + j);
                s_krem = k1 - next;
            }
            run = next;
        }
    }
    __syncthreads();

    if (mode != 0) {
        if (tid == 0)
            g_thr = (mode == 1) ? __int_as_float(0x7f800000) : 0.0f;
        return;
    }

    // fine phase: parallel suffix-select over 256 bins of coarse bin s_bin
    const unsigned b2 = s_bin;
    const unsigned krem = s_krem;
    unsigned fh = 0, fv = 0;
    if (tid < 256) {
        fh = g_fine[(b2 << 8) | (unsigned)tid];
        fv = fh;
#pragma unroll
        for (int d = 1; d < 32; d <<= 1) {
            unsigned u = __shfl_down_sync(0xffffffffu, fv, d);
            if (lane + d < 32) fv += u;
        }
        if (lane == 0) fwsum[wid] = fv;
    }
    __syncthreads();
    if (tid < 8) {
        unsigned acc = 0;
        for (int j = tid + 1; j < 8; j++) acc += fwsum[j];
        fwsuf[tid] = acc;
    }
    __syncthreads();
    if (tid < 256) {
        unsigned fsfx = fv + fwsuf[wid];       // suffix starting at this bin
        unsigned nxt = fsfx - fh;
        if (fsfx >= krem && nxt < krem) {
            unsigned key = (g_p1 << 20) | (b2 << 8) | (unsigned)tid;
            g_thr = neg_loss_f(key2f(key));
        }
    }
}

// ---------------------------------------------------------------------------
__device__ __forceinline__ float lane_loss(float x, unsigned cls, float thr) {
    float ax  = fabsf(x);
    float lse = lse_fast(ax);
    float pl  = fmaxf(-x, 0.0f) + lse;
    float nl  = fmaxf( x, 0.0f) + lse;
    float r = 0.0f;
    if (cls == 1u) r = pl;
    else if (cls == 2u) r = (nl < thr) ? nl : 0.0f;
    return r;
}
__device__ __forceinline__ float elem_loss_t(float x, float t, float thr) {
    unsigned cls = (t > 0.f) ? 1u : ((t < 0.f) ? 2u : 0u);
    return lane_loss(x, cls, thr);
}

__global__ void finalize_kernel(const float* __restrict__ in,
                                const float* __restrict__ tg,
                                float* __restrict__ out, int n) {
    const float thr = g_thr;
    const float4* in4 = (const float4*)in;
    float4* o4 = (float4*)out;
    const int n4 = n >> 2;
    const int S = gridDim.x * blockDim.x;
    int i = blockIdx.x * blockDim.x + threadIdx.x;

    for (; i + S < n4; i += 2 * S) {
        float4 x0 = in4[i];
        float4 x1 = in4[i + S];
        unsigned c0 = g_code[i];
        unsigned c1 = g_code[i + S];
        float4 o0, o1;
        o0.x = lane_loss(x0.x,  c0        & 3u, thr);
        o0.y = lane_loss(x0.y, (c0 >> 2)  & 3u, thr);
        o0.z = lane_loss(x0.z, (c0 >> 4)  & 3u, thr);
        o0.w = lane_loss(x0.w, (c0 >> 6)  & 3u, thr);
        o1.x = lane_loss(x1.x,  c1        & 3u, thr);
        o1.y = lane_loss(x1.y, (c1 >> 2)  & 3u, thr);
        o1.z = lane_loss(x1.z, (c1 >> 4)  & 3u, thr);
        o1.w = lane_loss(x1.w, (c1 >> 6)  & 3u, thr);
        o4[i] = o0;
        o4[i + S] = o1;
    }
    for (; i < n4; i += S) {
        float4 x0 = in4[i];
        unsigned c0 = g_code[i];
        float4 o0;
        o0.x = lane_loss(x0.x,  c0        & 3u, thr);
        o0.y = lane_loss(x0.y, (c0 >> 2)  & 3u, thr);
        o0.z = lane_loss(x0.z, (c0 >> 4)  & 3u, thr);
        o0.w = lane_loss(x0.w, (c0 >> 6)  & 3u, thr);
        o4[i] = o0;
    }
    if (blockIdx.x == 0) {
        for (int j = (n4 << 2) + threadIdx.x; j < n; j += blockDim.x)
            out[j] = elem_loss_t(in[j], tg[j], thr);
    }
}

// ---------------------------------------------------------------------------
extern "C" void kernel_launch(void* const* d_in, const int* in_sizes, int n_in,
                              void* d_out, int out_size) {
    const float* inp  = (const float*)d_in[0];
    const float* tgt  = (const float*)d_in[1];
    const int*   kptr = (const int*)d_in[2];
    float* out = (float*)d_out;
    const int n = in_sizes[0];

    passA_kernel<<<1184, 256>>>(inp, tgt, n);
    select0_kernel<<<1, 1024>>>(kptr);
    passB_kernel<<<1184, 256>>>();
    select12_kernel<<<1, 1024>>>();
    finalize_kernel<<<1184, 256>>>(inp, tgt, out, n);
}

// round 11
// speedup vs baseline: 1.2855x; 1.0059x over previous
#include <cuda_runtime.h>
#include <cstdint>

// ---------------------------------------------------------------------------
// LargeLoss via radix-select on RAW INPUT BITS (softplus is monotone, so the
// kth-largest unobserved loss == softplus(kth-largest x among t<0)).
// R11: 3 launches — selects fused into the big kernels (redundant per-block
// recompute from kernel-boundary-consistent global state; no grid sync).
//   passA    : zero g_fine (+hist2 by block0); stream in+tg -> hist1 (top 12
//              key bits) + compacted candidate keys + class codes
//   passB    : per-block select0 from hist1+k (publish mode/p1/k1);
//              scan keys; in-bucket: smem hist2[d>>8] + global fine[d]
//   finalize : per-block select12 from hist2+fine -> thr; stream in+codes ->
//              losses; block0 zeroes hist1 + g_cnt for next replay
// ---------------------------------------------------------------------------

#define N_MAX 10240000
#define FINE_BINS (1u << 20)

__device__ unsigned g_keys[N_MAX];
__device__ unsigned char g_code[N_MAX / 4 + 8];   // 2 bits/elem, 1 byte per float4
__device__ unsigned g_hist1[4096];                // zeroed by finalize block 0
__device__ unsigned g_hist2[4096];                // zeroed by passA block 0
__device__ unsigned g_fine[FINE_BINS];            // zeroed by passA (grid)
__device__ unsigned g_cnt;                        // zeroed by finalize block 0
__device__ unsigned g_k1;                         // published by passB
__device__ unsigned g_p1;                         // published by passB
__device__ int      g_mode;                       // published by passB
// ---------------------------------------------------------------------------
__device__ __forceinline__ unsigned f2key(float x) {
    unsigned b = __float_as_uint(x);
    return (b & 0x80000000u) ? ~b : (b | 0x80000000u);
}
__device__ __forceinline__ float key2f(unsigned k) {
    unsigned b = (k & 0x80000000u) ? (k & 0x7FFFFFFFu) : ~k;
    return __uint_as_float(b);
}
// fast softplus pieces: lse = log(1 + e^-|x|), via MUFU intrinsics.
__device__ __forceinline__ float lse_fast(float ax) {
    return __logf(1.0f + __expf(-ax));
}
__device__ __forceinline__ float neg_loss_f(float x) {   // softplus(x)
    return fmaxf(x, 0.0f) + lse_fast(fabsf(x));
}
// inclusive suffix scan within a warp
__device__ __forceinline__ unsigned warp_sufscan(unsigned v, int lane) {
#pragma unroll
    for (int d = 1; d < 32; d <<= 1) {
        unsigned u = __shfl_down_sync(0xffffffffu, v, d);
        if (lane + d < 32) v += u;
    }
    return v;
}

// ---------------------------------------------------------------------------
// Pass A: zero scratch; histogram (bits 31:20 of key), candidate key
// compaction (shared-staged), class code per float4.
__global__ void passA_kernel(const float* __restrict__ in,
                             const float* __restrict__ tg, int n) {
    __shared__ unsigned hist[4096];
    __shared__ unsigned stage[4096];
    __shared__ unsigned s_cnt, s_base;

    const int tid = threadIdx.x, bs = blockDim.x;
    const int lane = tid & 31;
    for (int i = tid; i < 4096; i += bs) hist[i] = 0u;
    if (tid == 0) s_cnt = 0u;

    // zero g_fine (grid) and g_hist2 (block 0) for this replay's passB
    {
        const unsigned t = blockIdx.x * bs + tid;
        const unsigned S = gridDim.x * bs;
        uint4* f4 = (uint4*)g_fine;
        const unsigned M4 = FINE_BINS / 4;
        for (unsigned i = t; i < M4; i += S) f4[i] = make_uint4(0u, 0u, 0u, 0u);
    }
    if (blockIdx.x == 0) {
        for (int i = tid; i < 4096; i += bs) g_hist2[i] = 0u;
    }
    __syncthreads();

    const float4* in4 = (const float4*)in;
    const float4* tg4 = (const float4*)tg;
    const int n4 = n >> 2;
    const int step = gridDim.x * bs * 2;

    for (int base = blockIdx.x * bs * 2; base < n4; base += step) {
        int i0 = base + tid;
        int i1 = base + bs + tid;
        bool v0 = i0 < n4, v1 = i1 < n4;
        float4 x0, t0, x1, t1;
        if (v0) { x0 = in4[i0]; t0 = tg4[i0]; }
        if (v1) { x1 = in4[i1]; t1 = tg4[i1]; }

        // class per lane: 0 unobserved, 1 positive, 2 negative
        int c0 = 0, c1 = 0;
        if (v0) {
            unsigned a = (t0.x > 0.f) ? 1u : ((t0.x < 0.f) ? 2u : 0u);
            unsigned b = (t0.y > 0.f) ? 1u : ((t0.y < 0.f) ? 2u : 0u);
            unsigned c = (t0.z > 0.f) ? 1u : ((t0.z < 0.f) ? 2u : 0u);
            unsigned d = (t0.w > 0.f) ? 1u : ((t0.w < 0.f) ? 2u : 0u);
            g_code[i0] = (unsigned char)(a | (b << 2) | (c << 4) | (d << 6));
            c0 = (a == 2u) + (b == 2u) + (c == 2u) + (d == 2u);
        }
        if (v1) {
            unsigned a = (t1.x > 0.f) ? 1u : ((t1.x < 0.f) ? 2u : 0u);
            unsigned b = (t1.y > 0.f) ? 1u : ((t1.y < 0.f) ? 2u : 0u);
            unsigned c = (t1.z > 0.f) ? 1u : ((t1.z < 0.f) ? 2u : 0u);
            unsigned d = (t1.w > 0.f) ? 1u : ((t1.w < 0.f) ? 2u : 0u);
            g_code[i1] = (unsigned char)(a | (b << 2) | (c << 4) | (d << 6));
            c1 = (a == 2u) + (b == 2u) + (c == 2u) + (d == 2u);
        }
        unsigned cnt = (unsigned)(c0 + c1);

        unsigned inc = cnt;
#pragma unroll
        for (int d = 1; d < 32; d <<= 1) {
            unsigned u = __shfl_up_sync(0xffffffffu, inc, d);
            if (lane >= d) inc += u;
        }
        unsigned wtot = __shfl_sync(0xffffffffu, inc, 31);
        unsigned wbase = 0;
        if (lane == 0 && wtot) wbase = atomicAdd(&s_cnt, wtot);
        wbase = __shfl_sync(0xffffffffu, wbase, 0);
        unsigned p = wbase + (inc - cnt);

#define PUSH(xv, tv) do { if ((tv) < 0.f) {                       \
            unsigned kk = f2key(xv);                              \
            atomicAdd(&hist[kk >> 20], 1u);                       \
            stage[p++] = kk; } } while (0)
        if (v0) { PUSH(x0.x, t0.x); PUSH(x0.y, t0.y); PUSH(x0.z, t0.z); PUSH(x0.w, t0.w); }
        if (v1) { PUSH(x1.x, t1.x); PUSH(x1.y, t1.y); PUSH(x1.z, t1.z); PUSH(x1.w, t1.w); }
#undef PUSH

        __syncthreads();
        unsigned c = s_cnt;
        if (c >= 2048u) {
            if (tid == 0) s_base = atomicAdd(&g_cnt, c);
            __syncthreads();
            unsigned gb = s_base;
            for (unsigned j = tid; j < c; j += bs) g_keys[gb + j] = stage[j];
            __syncthreads();
            if (tid == 0) s_cnt = 0u;
            __syncthreads();
        }
    }

    // scalar tail (n % 4), block 0 only — uniform loop for warp ops
    if (blockIdx.x == 0) {
        for (int base = (n >> 2) << 2; base < n; base += bs) {
            int i = base + tid;
            unsigned cnt = 0; unsigned kk = 0;
            if (i < n && tg[i] < 0.f) { kk = f2key(in[i]); cnt = 1; atomicAdd(&hist[kk >> 20], 1u); }
            unsigned inc = cnt;
#pragma unroll
            for (int d = 1; d < 32; d <<= 1) {
                unsigned u = __shfl_up_sync(0xffffffffu, inc, d);
                if (lane >= d) inc += u;
            }
            unsigned wtot = __shfl_sync(0xffffffffu, inc, 31);
            unsigned wbase = 0;
            if (lane == 0 && wtot) wbase = atomicAdd(&s_cnt, wtot);
            wbase = __shfl_sync(0xffffffffu, wbase, 0);
            if (cnt) stage[wbase + inc - 1] = kk;
        }
    }

    __syncthreads();
    unsigned c = s_cnt;
    if (c > 0u) {
        if (tid == 0) s_base = atomicAdd(&g_cnt, c);
        __syncthreads();
        unsigned gb = s_base;
        for (unsigned j = tid; j < c; j += bs) g_keys[gb + j] = stage[j];
    }
    __syncthreads();
    for (int i = tid; i < 4096; i += bs) {
        unsigned hv = hist[i];
        if (hv) atomicAdd(&g_hist1[i], hv);
    }
}

// ---------------------------------------------------------------------------
// Pass B: per-block select0 (hist1 + k -> p1, k1, mode; publish), then scan
// keys: in-bucket -> smem coarse hist (bits 19:8) + global fine hist (20 bits).
__global__ void passB_kernel(const int* __restrict__ kptr) {
    __shared__ unsigned hist[4096];
    __shared__ unsigned wsumA[8], wsufA[8];
    __shared__ unsigned s_p1, s_k1;

    const int tid = threadIdx.x, bs = blockDim.x;   // bs == 256
    const int lane = tid & 31, wid = tid >> 5;

    // ---- per-block select0 over g_hist1 (16 bins per thread) ----
    unsigned h[16]; unsigned sum = 0;
    {
        const uint4* h4 = (const uint4*)g_hist1;
#pragma unroll
        for (int j = 0; j < 4; j++) {
            uint4 q = h4[tid * 4 + j];
            h[j * 4 + 0] = q.x; h[j * 4 + 1] = q.y;
            h[j * 4 + 2] = q.z; h[j * 4 + 3] = q.w;
            sum += q.x + q.y + q.z + q.w;
        }
    }
    unsigned v = warp_sufscan(sum, lane);
    if (lane == 0) wsumA[wid] = v;
    if (tid == 0) { s_p1 = 0u; s_k1 = 0u; }
    __syncthreads();
    if (tid < 8) {
        unsigned acc = 0;
        for (int j = tid + 1; j < 8; j++) acc += wsumA[j];
        wsufA[tid] = acc;
    }
    __syncthreads();
    const unsigned total = wsufA[0] + wsumA[0];
    int kraw = *kptr;
    const unsigned kk = (kraw > 0) ? (unsigned)kraw : 0u;
    const int mode = (kk == 0u) ? 1 : ((kk > total) ? 2 : 0);
    if (mode == 0) {
        unsigned run = v + wsufA[wid];
#pragma unroll
        for (int j = 0; j < 16; j++) {
            unsigned nxt = run - h[j];
            if (run >= kk && nxt < kk) { s_p1 = (unsigned)(tid * 16 + j); s_k1 = kk - nxt; }
            run = nxt;
        }
    }
    __syncthreads();
    if (tid == 0) { g_mode = mode; g_p1 = s_p1; g_k1 = s_k1; }  // identical in all blocks
    if (mode != 0) return;   // hist2/fine stay zero; finalize shortcuts on mode

    // ---- main scan ----
    for (int i = tid; i < 4096; i += bs) hist[i] = 0u;
    __syncthreads();

    const unsigned cnt = g_cnt;
    const unsigned lo  = s_p1 << 20;   // bucket base in key space
    const uint4* k4 = (const uint4*)g_keys;
    const unsigned m4 = cnt >> 2;
    const unsigned S = gridDim.x * bs;
    unsigned i = blockIdx.x * bs + tid;

#define PROC(e) do {                                              \
        unsigned _dv = (e) - lo;                                  \
        if (_dv < 0x100000u) {                                    \
            atomicAdd(&hist[_dv >> 8], 1u);                       \
            atomicAdd(&g_fine[_dv], 1u);                          \
        } } while (0)
#define PROCQ(q) do { PROC((q).x); PROC((q).y); PROC((q).z); PROC((q).w); } while (0)
    for (; i + S < m4; i += 2u * S) {
        uint4 qa = k4[i], qb = k4[i + S];
        PROCQ(qa); PROCQ(qb);
    }
    for (; i < m4; i += S) { uint4 qa = k4[i]; PROCQ(qa); }
    if (blockIdx.x == 0) {
        for (unsigned j = (m4 << 2) + tid; j < cnt; j += bs) PROC(g_keys[j]);
    }
#undef PROCQ
#undef PROC
    __syncthreads();
    for (int i2 = tid; i2 < 4096; i2 += bs) {
        unsigned hv = hist[i2];
        if (hv) atomicAdd(&g_hist2[i2], hv);
    }
}

// ---------------------------------------------------------------------------
__device__ __forceinline__ float lane_loss(float x, unsigned cls, float thr) {
    float ax  = fabsf(x);
    float lse = lse_fast(ax);
    float pl  = fmaxf(-x, 0.0f) + lse;
    float nl  = fmaxf( x, 0.0f) + lse;
    float r = 0.0f;
    if (cls == 1u) r = pl;
    else if (cls == 2u) r = (nl < thr) ? nl : 0.0f;
    return r;
}
__device__ __forceinline__ float elem_loss_t(float x, float t, float thr) {
    unsigned cls = (t > 0.f) ? 1u : ((t < 0.f) ? 2u : 0u);
    return lane_loss(x, cls, thr);
}

// Finalize: per-block select12 (hist2 + fine -> threshold), then stream.
// Block 0 also re-zeroes hist1 and g_cnt for the next replay.
__global__ void finalize_kernel(const float* __restrict__ in,
                                const float* __restrict__ tg,
                                float* __restrict__ out, int n) {
    __shared__ unsigned wsumB[8], wsufB[8];
    __shared__ unsigned s_bin, s_krem;
    __shared__ float s_thr;

    const int tid = threadIdx.x, bs = blockDim.x;   // bs == 256
    const int lane = tid & 31, wid = tid >> 5;
    const int mode = g_mode;

    float thr;
    if (mode == 1)      thr = __int_as_float(0x7f800000);  // keep all
    else if (mode == 2) thr = 0.0f;                        // drop all negs
    else {
        const unsigned k1 = g_k1;
        const unsigned p1 = g_p1;
        // coarse select over g_hist2 (16 bins per thread)
        unsigned h[16]; unsigned sum = 0;
        {
            const uint4* h4 = (const uint4*)g_hist2;
#pragma unroll
            for (int j = 0; j < 4; j++) {
                uint4 q = h4[tid * 4 + j];
                h[j * 4 + 0] = q.x; h[j * 4 + 1] = q.y;
                h[j * 4 + 2] = q.z; h[j * 4 + 3] = q.w;
                sum += q.x + q.y + q.z + q.w;
            }
        }
        unsigned v = warp_sufscan(sum, lane);
        if (lane == 0) wsumB[wid] = v;
        if (tid == 0) { s_bin = 0u; s_krem = 1u; }
        __syncthreads();
        if (tid < 8) {
            unsigned acc = 0;
            for (int j = tid + 1; j < 8; j++) acc += wsumB[j];
            wsufB[tid] = acc;
        }
        __syncthreads();
        {
            unsigned run = v + wsufB[wid];
#pragma unroll
            for (int j = 0; j < 16; j++) {
                unsigned nxt = run - h[j];
                if (run >= k1 && nxt < k1) { s_bin = (unsigned)(tid * 16 + j); s_krem = k1 - nxt; }
                run = nxt;
            }
        }
        __syncthreads();
        // fine select over 256 bins of coarse bin s_bin (1 per thread)
        const unsigned b2 = s_bin;
        const unsigned krem = s_krem;
        unsigned fh = g_fine[(b2 << 8) | (unsigned)tid];
        unsigned fv = warp_sufscan(fh, lane);
        if (lane == 0) wsumB[wid] = fv;
        __syncthreads();
        if (tid < 8) {
            unsigned acc = 0;
            for (int j = tid + 1; j < 8; j++) acc += wsumB[j];
            wsufB[tid] = acc;
        }
        __syncthreads();
        {
            unsigned fsfx = fv + wsufB[wid];
            unsigned nxt = fsfx - fh;
            if (fsfx >= krem && nxt < krem)
                s_thr = neg_loss_f(key2f((p1 << 20) | (b2 << 8) | (unsigned)tid));
        }
        __syncthreads();
        thr = s_thr;
    }

    // reset replay state (nothing reads hist1/g_cnt after passB)
    if (blockIdx.x == 0) {
        for (int i = tid; i < 4096; i += bs) g_hist1[i] = 0u;
        if (tid == 0) g_cnt = 0u;
    }

    const float4* in4 = (const float4*)in;
    float4* o4 = (float4*)out;
    const int n4 = n >> 2;
    const int S = gridDim.x * bs;
    int i = blockIdx.x * bs + tid;

    for (; i + S < n4; i += 2 * S) {
        float4 x0 = in4[i];
        float4 x1 = in4[i + S];
        unsigned c0 = g_code[i];
        unsigned c1 = g_code[i + S];
        float4 o0, o1;
        o0.x = lane_loss(x0.x,  c0        & 3u, thr);
        o0.y = lane_loss(x0.y, (c0 >> 2)  & 3u, thr);
        o0.z = lane_loss(x0.z, (c0 >> 4)  & 3u, thr);
        o0.w = lane_loss(x0.w, (c0 >> 6)  & 3u, thr);
        o1.x = lane_loss(x1.x,  c1        & 3u, thr);
        o1.y = lane_loss(x1.y, (c1 >> 2)  & 3u, thr);
        o1.z = lane_loss(x1.z, (c1 >> 4)  & 3u, thr);
        o1.w = lane_loss(x1.w, (c1 >> 6)  & 3u, thr);
        o4[i] = o0;
        o4[i + S] = o1;
    }
    for (; i < n4; i += S) {
        float4 x0 = in4[i];
        unsigned c0 = g_code[i];
        float4 o0;
        o0.x = lane_loss(x0.x,  c0        & 3u, thr);
        o0.y = lane_loss(x0.y, (c0 >> 2)  & 3u, thr);
        o0.z = lane_loss(x0.z, (c0 >> 4)  & 3u, thr);
        o0.w = lane_loss(x0.w, (c0 >> 6)  & 3u, thr);
        o4[i] = o0;
    }
    if (blockIdx.x == 0) {
        for (int j = (n4 << 2) + tid; j < n; j += bs)
            out[j] = elem_loss_t(in[j], tg[j], thr);
    }
}

// ---------------------------------------------------------------------------
extern "C" void kernel_launch(void* const* d_in, const int* in_sizes, int n_in,
                              void* d_out, int out_size) {
    const float* inp  = (const float*)d_in[0];
    const float* tgt  = (const float*)d_in[1];
    const int*   kptr = (const int*)d_in[2];
    float* out = (float*)d_out;
    const int n = in_sizes[0];

    passA_kernel<<<1184, 256>>>(inp, tgt, n);
    passB_kernel<<<1184, 256>>>(kptr);
    finalize_kernel<<<1184, 256>>>(inp, tgt, out, n);
}

// round 12
// speedup vs baseline: 1.4241x; 1.1078x over previous
#include <cuda_runtime.h>
#include <cstdint>

// ---------------------------------------------------------------------------
// LargeLoss via radix-select on RAW INPUT BITS (softplus is monotone, so the
// kth-largest unobserved loss == softplus(kth-largest x among t<0)).
// R12: no key compaction. 3 lean streaming kernels:
//   passA    : zero g_fine (+hist2 by block0); stream in+tg -> class codes +
//              smem hist of top-12 key bits -> g_hist1
//   passB    : per-block select0 from hist1+k (publish mode/p1/k1); stream
//              in+codes; cls==2 & in-bucket -> smem hist2[d>>8] + g_fine[d]
//   finalize : per-block select12 from hist2+fine -> thr; stream in+codes ->
//              losses; block0 zeroes hist1 for next replay
// ---------------------------------------------------------------------------

#define FINE_BINS (1u << 20)
#define N_MAXQ (10240000 / 4 + 8)

__device__ unsigned char g_code[N_MAXQ];          // 2 bits/elem, 1 byte per float4
__device__ unsigned g_hist1[4096];                // zeroed by finalize block 0
__device__ unsigned g_hist2[4096];                // zeroed by passA block 0
__device__ unsigned g_fine[FINE_BINS];            // zeroed by passA (grid)
__device__ unsigned g_k1;                         // published by passB
__device__ unsigned g_p1;                         // published by passB
__device__ int      g_mode;                       // published by passB

// ---------------------------------------------------------------------------
__device__ __forceinline__ unsigned f2key(float x) {
    unsigned b = __float_as_uint(x);
    return (b & 0x80000000u) ? ~b : (b | 0x80000000u);
}
__device__ __forceinline__ float key2f(unsigned k) {
    unsigned b = (k & 0x80000000u) ? (k & 0x7FFFFFFFu) : ~k;
    return __uint_as_float(b);
}
// fast softplus pieces: lse = log(1 + e^-|x|), via MUFU intrinsics.
__device__ __forceinline__ float lse_fast(float ax) {
    return __logf(1.0f + __expf(-ax));
}
__device__ __forceinline__ float neg_loss_f(float x) {   // softplus(x)
    return fmaxf(x, 0.0f) + lse_fast(fabsf(x));
}
// inclusive suffix scan within a warp
__device__ __forceinline__ unsigned warp_sufscan(unsigned v, int lane) {
#pragma unroll
    for (int d = 1; d < 32; d <<= 1) {
        unsigned u = __shfl_down_sync(0xffffffffu, v, d);
        if (lane + d < 32) v += u;
    }
    return v;
}

// ---------------------------------------------------------------------------
// Pass A: zero scratch; stream in+tg -> class codes + 12-bit key histogram.
__global__ void passA_kernel(const float* __restrict__ in,
                             const float* __restrict__ tg, int n) {
    __shared__ unsigned hist[4096];
    const int tid = threadIdx.x, bs = blockDim.x;
    for (int i = tid; i < 4096; i += bs) hist[i] = 0u;

    // zero g_fine (grid) and g_hist2 (block 0) for this replay
    {
        const unsigned t = blockIdx.x * bs + tid;
        const unsigned S = gridDim.x * bs;
        uint4* f4 = (uint4*)g_fine;
        const unsigned M4 = FINE_BINS / 4;
        for (unsigned i = t; i < M4; i += S) f4[i] = make_uint4(0u, 0u, 0u, 0u);
    }
    if (blockIdx.x == 0) {
        for (int i = tid; i < 4096; i += bs) g_hist2[i] = 0u;
    }
    __syncthreads();

    const float4* in4 = (const float4*)in;
    const float4* tg4 = (const float4*)tg;
    const int n4 = n >> 2;
    const int S = gridDim.x * bs;
    int i = blockIdx.x * bs + tid;

#define CLS(tv) ((tv) < 0.f ? 2u : ((tv) > 0.f ? 1u : 0u))
#define HISTQ(xq, tq) do {                                                   \
        if ((tq).x < 0.f) atomicAdd(&hist[f2key((xq).x) >> 20], 1u);         \
        if ((tq).y < 0.f) atomicAdd(&hist[f2key((xq).y) >> 20], 1u);         \
        if ((tq).z < 0.f) atomicAdd(&hist[f2key((xq).z) >> 20], 1u);         \
        if ((tq).w < 0.f) atomicAdd(&hist[f2key((xq).w) >> 20], 1u); } while (0)

    for (; i + S < n4; i += 2 * S) {
        float4 x0 = in4[i],     t0 = tg4[i];
        float4 x1 = in4[i + S], t1 = tg4[i + S];
        g_code[i]     = (unsigned char)(CLS(t0.x) | (CLS(t0.y) << 2) |
                                        (CLS(t0.z) << 4) | (CLS(t0.w) << 6));
        g_code[i + S] = (unsigned char)(CLS(t1.x) | (CLS(t1.y) << 2) |
                                        (CLS(t1.z) << 4) | (CLS(t1.w) << 6));
        HISTQ(x0, t0);
        HISTQ(x1, t1);
    }
    for (; i < n4; i += S) {
        float4 x0 = in4[i], t0 = tg4[i];
        g_code[i] = (unsigned char)(CLS(t0.x) | (CLS(t0.y) << 2) |
                                    (CLS(t0.z) << 4) | (CLS(t0.w) << 6));
        HISTQ(x0, t0);
    }
    // scalar tail (n % 4), block 0: histogram only (finalize tail uses tg)
    if (blockIdx.x == 0) {
        for (int j = (n4 << 2) + tid; j < n; j += bs)
            if (tg[j] < 0.f) atomicAdd(&hist[f2key(in[j]) >> 20], 1u);
    }
#undef HISTQ
#undef CLS

    __syncthreads();
    for (int i2 = tid; i2 < 4096; i2 += bs) {
        unsigned hv = hist[i2];
        if (hv) atomicAdd(&g_hist1[i2], hv);
    }
}

// ---------------------------------------------------------------------------
// Pass B: per-block select0 (hist1 + k -> p1, k1, mode; publish), then stream
// in+codes: cls==2 & in-bucket -> smem hist2[d>>8] + global fine[d].
__global__ void passB_kernel(const float* __restrict__ in,
                             const float* __restrict__ tg,
                             const int* __restrict__ kptr, int n) {
    __shared__ unsigned hist[4096];
    __shared__ unsigned wsumA[8], wsufA[8];
    __shared__ unsigned s_p1, s_k1;

    const int tid = threadIdx.x, bs = blockDim.x;   // bs == 256
    const int lane = tid & 31, wid = tid >> 5;

    // ---- per-block select0 over g_hist1 (16 bins per thread) ----
    unsigned h[16]; unsigned sum = 0;
    {
        const uint4* h4 = (const uint4*)g_hist1;
#pragma unroll
        for (int j = 0; j < 4; j++) {
            uint4 q = h4[tid * 4 + j];
            h[j * 4 + 0] = q.x; h[j * 4 + 1] = q.y;
            h[j * 4 + 2] = q.z; h[j * 4 + 3] = q.w;
            sum += q.x + q.y + q.z + q.w;
        }
    }
    unsigned v = warp_sufscan(sum, lane);
    if (lane == 0) wsumA[wid] = v;
    if (tid == 0) { s_p1 = 0u; s_k1 = 0u; }
    __syncthreads();
    if (tid < 8) {
        unsigned acc = 0;
        for (int j = tid + 1; j < 8; j++) acc += wsumA[j];
        wsufA[tid] = acc;
    }
    __syncthreads();
    const unsigned total = wsufA[0] + wsumA[0];
    int kraw = *kptr;
    const unsigned kk = (kraw > 0) ? (unsigned)kraw : 0u;
    const int mode = (kk == 0u) ? 1 : ((kk > total) ? 2 : 0);
    if (mode == 0) {
        unsigned run = v + wsufA[wid];
#pragma unroll
        for (int j = 0; j < 16; j++) {
            unsigned nxt = run - h[j];
            if (run >= kk && nxt < kk) { s_p1 = (unsigned)(tid * 16 + j); s_k1 = kk - nxt; }
            run = nxt;
        }
    }
    __syncthreads();
    if (tid == 0) { g_mode = mode; g_p1 = s_p1; g_k1 = s_k1; }  // identical in all blocks
    if (mode != 0) return;   // hist2/fine stay zero; finalize shortcuts on mode

    // ---- main scan over in + codes ----
    for (int i = tid; i < 4096; i += bs) hist[i] = 0u;
    __syncthreads();

    const unsigned lo = s_p1 << 20;   // bucket base in key space
    const float4* in4 = (const float4*)in;
    const int n4 = n >> 2;
    const int S = gridDim.x * bs;
    int i = blockIdx.x * bs + tid;

#define PB(xv, cq, sh) do {                                                  \
        if ((((cq) >> (sh)) & 3u) == 2u) {                                   \
            unsigned _dv = f2key(xv) - lo;                                   \
            if (_dv < 0x100000u) {                                           \
                atomicAdd(&hist[_dv >> 8], 1u);                              \
                atomicAdd(&g_fine[_dv], 1u);                                 \
            } } } while (0)
#define PBQ(xq, cq) do { PB((xq).x, cq, 0); PB((xq).y, cq, 2);               \
                         PB((xq).z, cq, 4); PB((xq).w, cq, 6); } while (0)
    for (; i + S < n4; i += 2 * S) {
        float4 x0 = in4[i],     x1 = in4[i + S];
        unsigned c0 = g_code[i], c1 = g_code[i + S];
        PBQ(x0, c0);
        PBQ(x1, c1);
    }
    for (; i < n4; i += S) {
        float4 x0 = in4[i];
        unsigned c0 = g_code[i];
        PBQ(x0, c0);
    }
    if (blockIdx.x == 0) {
        for (int j = (n4 << 2) + tid; j < n; j += bs) {
            if (tg[j] < 0.f) {
                unsigned dv = f2key(in[j]) - lo;
                if (dv < 0x100000u) {
                    atomicAdd(&hist[dv >> 8], 1u);
                    atomicAdd(&g_fine[dv], 1u);
                }
            }
        }
    }
#undef PBQ
#undef PB
    __syncthreads();
    for (int i2 = tid; i2 < 4096; i2 += bs) {
        unsigned hv = hist[i2];
        if (hv) atomicAdd(&g_hist2[i2], hv);
    }
}

// ---------------------------------------------------------------------------
__device__ __forceinline__ float lane_loss(float x, unsigned cls, float thr) {
    float ax  = fabsf(x);
    float lse = lse_fast(ax);
    float pl  = fmaxf(-x, 0.0f) + lse;
    float nl  = fmaxf( x, 0.0f) + lse;
    float r = 0.0f;
    if (cls == 1u) r = pl;
    else if (cls == 2u) r = (nl < thr) ? nl : 0.0f;
    return r;
}
__device__ __forceinline__ float elem_loss_t(float x, float t, float thr) {
    unsigned cls = (t > 0.f) ? 1u : ((t < 0.f) ? 2u : 0u);
    return lane_loss(x, cls, thr);
}

// Finalize: per-block select12 (hist2 + fine -> threshold), then stream.
// Block 0 also re-zeroes hist1 for the next replay.
__global__ void finalize_kernel(const float* __restrict__ in,
                                const float* __restrict__ tg,
                                float* __restrict__ out, int n) {
    __shared__ unsigned wsumB[8], wsufB[8];
    __shared__ unsigned s_bin, s_krem;
    __shared__ float s_thr;

    const int tid = threadIdx.x, bs = blockDim.x;   // bs == 256
    const int lane = tid & 31, wid = tid >> 5;
    const int mode = g_mode;

    float thr;
    if (mode == 1)      thr = __int_as_float(0x7f800000);  // keep all
    else if (mode == 2) thr = 0.0f;                        // drop all negs
    else {
        const unsigned k1 = g_k1;
        const unsigned p1 = g_p1;
        // coarse select over g_hist2 (16 bins per thread)
        unsigned h[16]; unsigned sum = 0;
        {
            const uint4* h4 = (const uint4*)g_hist2;
#pragma unroll
            for (int j = 0; j < 4; j++) {
                uint4 q = h4[tid * 4 + j];
                h[j * 4 + 0] = q.x; h[j * 4 + 1] = q.y;
                h[j * 4 + 2] = q.z; h[j * 4 + 3] = q.w;
                sum += q.x + q.y + q.z + q.w;
            }
        }
        unsigned v = warp_sufscan(sum, lane);
        if (lane == 0) wsumB[wid] = v;
        if (tid == 0) { s_bin = 0u; s_krem = 1u; }
        __syncthreads();
        if (tid < 8) {
            unsigned acc = 0;
            for (int j = tid + 1; j < 8; j++) acc += wsumB[j];
            wsufB[tid] = acc;
        }
        __syncthreads();
        {
            unsigned run = v + wsufB[wid];
#pragma unroll
            for (int j = 0; j < 16; j++) {
                unsigned nxt = run - h[j];
                if (run >= k1 && nxt < k1) { s_bin = (unsigned)(tid * 16 + j); s_krem = k1 - nxt; }
                run = nxt;
            }
        }
        __syncthreads();
        // fine select over 256 bins of coarse bin s_bin (1 per thread)
        const unsigned b2 = s_bin;
        const unsigned krem = s_krem;
        unsigned fh = g_fine[(b2 << 8) | (unsigned)tid];
        unsigned fv = warp_sufscan(fh, lane);
        if (lane == 0) wsumB[wid] = fv;
        __syncthreads();
        if (tid < 8) {
            unsigned acc = 0;
            for (int j = tid + 1; j < 8; j++) acc += wsumB[j];
            wsufB[tid] = acc;
        }
        __syncthreads();
        {
            unsigned fsfx = fv + wsufB[wid];
            unsigned nxt = fsfx - fh;
            if (fsfx >= krem && nxt < krem)
                s_thr = neg_loss_f(key2f((p1 << 20) | (b2 << 8) | (unsigned)tid));
        }
        __syncthreads();
        thr = s_thr;
    }

    // reset replay state (nothing reads hist1 after passB)
    if (blockIdx.x == 0) {
        for (int i = tid; i < 4096; i += bs) g_hist1[i] = 0u;
    }

    const float4* in4 = (const float4*)in;
    float4* o4 = (float4*)out;
    const int n4 = n >> 2;
    const int S = gridDim.x * bs;
    int i = blockIdx.x * bs + tid;

    for (; i + S < n4; i += 2 * S) {
        float4 x0 = in4[i];
        float4 x1 = in4[i + S];
        unsigned c0 = g_code[i];
        unsigned c1 = g_code[i + S];
        float4 o0, o1;
        o0.x = lane_loss(x0.x,  c0        & 3u, thr);
        o0.y = lane_loss(x0.y, (c0 >> 2)  & 3u, thr);
        o0.z = lane_loss(x0.z, (c0 >> 4)  & 3u, thr);
        o0.w = lane_loss(x0.w, (c0 >> 6)  & 3u, thr);
        o1.x = lane_loss(x1.x,  c1        & 3u, thr);
        o1.y = lane_loss(x1.y, (c1 >> 2)  & 3u, thr);
        o1.z = lane_loss(x1.z, (c1 >> 4)  & 3u, thr);
        o1.w = lane_loss(x1.w, (c1 >> 6)  & 3u, thr);
        o4[i] = o0;
        o4[i + S] = o1;
    }
    for (; i < n4; i += S) {
        float4 x0 = in4[i];
        unsigned c0 = g_code[i];
        float4 o0;
        o0.x = lane_loss(x0.x,  c0        & 3u, thr);
        o0.y = lane_loss(x0.y, (c0 >> 2)  & 3u, thr);
        o0.z = lane_loss(x0.z, (c0 >> 4)  & 3u, thr);
        o0.w = lane_loss(x0.w, (c0 >> 6)  & 3u, thr);
        o4[i] = o0;
    }
    if (blockIdx.x == 0) {
        for (int j = (n4 << 2) + tid; j < n; j += bs)
            out[j] = elem_loss_t(in[j], tg[j], thr);
    }
}

// ---------------------------------------------------------------------------
extern "C" void kernel_launch(void* const* d_in, const int* in_sizes, int n_in,
                              void* d_out, int out_size) {
    const float* inp  = (const float*)d_in[0];
    const float* tgt  = (const float*)d_in[1];
    const int*   kptr = (const int*)d_in[2];
    float* out = (float*)d_out;
    const int n = in_sizes[0];

    passA_kernel<<<1184, 256>>>(inp, tgt, n);
    passB_kernel<<<1184, 256>>>(inp, tgt, kptr, n);
    finalize_kernel<<<1184, 256>>>(inp, tgt, out, n);
}